// round 5
// baseline (speedup 1.0000x reference)
#include <cuda_runtime.h>
#include <cuda_bf16.h>
#include <math.h>

#define Bc 128
#define Tc 1024
#define Ic 128
#define Hc 1024
#define Oc 128
#define Gc 4096
#define KW 1280   // packed K: 1024 (W_eff) + 128 (W_x) + 128 (W_o/delta)
#define NBLK 132  // 128 gate CTAs + 4 y CTAs, all co-resident (148 SMs)

#define SA_BUF 4224   // 128 rows * 33 ull per buffer
#define SW_BUF 1056   // 32 rows * 33 ull per buffer
#define SMEM_BYTES ((2*SA_BUF + 2*SW_BUF) * 8)   // 84480 B

typedef unsigned long long ull;

// ---------- device scratch (static; no runtime allocation) ----------
__device__ float g_W[(size_t)Gc * KW];
__device__ float g_bp[Gc];
__device__ float g_h[2 * Bc * Hc];
__device__ float g_delta[Bc * Oc];

// ---------- grid barrier (release/acquire, no fences, no L1 flush) ----------
__device__ unsigned g_cnt = 0;
__device__ unsigned g_gen = 0;

__device__ __forceinline__ unsigned ld_acq(unsigned* p) {
    unsigned v;
    asm volatile("ld.acquire.gpu.global.u32 %0, [%1];" : "=r"(v) : "l"(p) : "memory");
    return v;
}
__device__ __forceinline__ void st_rel(unsigned* p, unsigned v) {
    asm volatile("st.release.gpu.global.u32 [%0], %1;" :: "l"(p), "r"(v) : "memory");
}
__device__ __forceinline__ unsigned atom_add_rel(unsigned* p, unsigned v) {
    unsigned old;
    asm volatile("atom.release.gpu.global.add.u32 %0, [%1], %2;"
                 : "=r"(old) : "l"(p), "r"(v) : "memory");
    return old;
}
__device__ __forceinline__ void grid_sync() {
    __syncthreads();
    if (threadIdx.x == 0) {
        unsigned my = ld_acq((unsigned*)&g_gen);
        if (atom_add_rel((unsigned*)&g_cnt, 1) == NBLK - 1) {
            g_cnt = 0;                         // ordered before release store below
            st_rel((unsigned*)&g_gen, my + 1);
        } else {
            while (ld_acq((unsigned*)&g_gen) == my) { }
        }
    }
    __syncthreads();
}

__device__ __forceinline__ void ffma2(ull& d, ull a, ull b) {
    asm("fma.rn.f32x2 %0, %1, %2, %0;" : "+l"(d) : "l"(a), "l"(b));
}
__device__ __forceinline__ ull packf2(float x, float y) {
    ull p; asm("mov.b64 %0, {%1, %2};" : "=l"(p) : "f"(x), "f"(y)); return p;
}
__device__ __forceinline__ float2 asf2(ull v) {
    float2 r; asm("mov.b64 {%0,%1}, %2;" : "=f"(r.x), "=f"(r.y) : "l"(v)); return r;
}
__device__ __forceinline__ float sigm(float x) { return 1.0f / (1.0f + expf(-x)); }

// ---------------- precompute: pack effective weights ----------------
__global__ void __launch_bounds__(256, 1) pack_weights(
    const float* __restrict__ Wih, const float* __restrict__ Whh,
    const float* __restrict__ bih, const float* __restrict__ bhh,
    const float* __restrict__ Wout, const float* __restrict__ bout)
{
    __shared__ float ao[32][129];
    __shared__ float wos[128][33];
    int cb = blockIdx.x, tid = threadIdx.x;

    for (int i = 0; i < 4; i++) {
        int idx = i * 256 + tid;
        int r = idx >> 5, c4 = idx & 31;
        int gr = ((r >> 3) << 10) + (cb << 3) + (r & 7);
        float4 v = *(const float4*)(Wih + (size_t)gr * 256 + 128 + (c4 << 2));
        ao[r][(c4 << 2) + 0] = v.x; ao[r][(c4 << 2) + 1] = v.y;
        ao[r][(c4 << 2) + 2] = v.z; ao[r][(c4 << 2) + 3] = v.w;
    }
    __syncthreads();

    int r = tid >> 3;
    int gr = ((r >> 3) << 10) + (cb << 3) + (r & 7);
    int kk0 = (tid & 7) << 2;
    for (int kc = 0; kc < 32; kc++) {
        for (int i = 0; i < 4; i++) {
            int idx = i * 256 + tid;
            int o = idx >> 3, c4 = idx & 7;
            float4 v = *(const float4*)(Wout + (size_t)o * Hc + (kc << 5) + (c4 << 2));
            wos[o][(c4 << 2) + 0] = v.x; wos[o][(c4 << 2) + 1] = v.y;
            wos[o][(c4 << 2) + 2] = v.z; wos[o][(c4 << 2) + 3] = v.w;
        }
        __syncthreads();
        float a0 = 0.f, a1 = 0.f, a2 = 0.f, a3 = 0.f;
#pragma unroll 4
        for (int o = 0; o < 128; o++) {
            float a = ao[r][o];
            a0 += a * wos[o][kk0 + 0]; a1 += a * wos[o][kk0 + 1];
            a2 += a * wos[o][kk0 + 2]; a3 += a * wos[o][kk0 + 3];
        }
        int k = (kc << 5) + kk0;
        const float* hh = Whh + (size_t)gr * Hc + k;
        float* dst = g_W + (size_t)(cb * 32 + r) * KW + k;
        dst[0] = hh[0] + a0; dst[1] = hh[1] + a1;
        dst[2] = hh[2] + a2; dst[3] = hh[3] + a3;
        __syncthreads();
    }
    for (int i = 0; i < 8; i++) {
        int idx = i * 256 + tid;
        int rr = idx >> 6, c4 = idx & 63;
        int grr = ((rr >> 3) << 10) + (cb << 3) + (rr & 7);
        float4 v = *(const float4*)(Wih + (size_t)grr * 256 + (c4 << 2));
        *(float4*)(g_W + (size_t)(cb * 32 + rr) * KW + 1024 + (c4 << 2)) = v;
    }
    if (tid < 32) {
        int grr = ((tid >> 3) << 10) + (cb << 3) + (tid & 7);
        float s = bih[grr] + bhh[grr];
        for (int o = 0; o < 128; o++) s += ao[tid][o] * bout[o];
        g_bp[cb * 32 + tid] = s;
    }
}

// ---------------- init h buffer + t=0 correction ----------------
__global__ void __launch_bounds__(256, 1) delta_init(
    const float* __restrict__ hn, const float* __restrict__ outt,
    const float* __restrict__ Wout, const float* __restrict__ bout)
{
    __shared__ __align__(16) float hs[Hc];
    int b = blockIdx.x, tid = threadIdx.x;
    for (int k = tid; k < Hc; k += 256) {
        float hv = hn[(size_t)b * Hc + k];
        hs[k] = hv;
        g_h[(size_t)b * Hc + k] = hv;
    }
    __syncthreads();
    if (tid < 128) {
        int o = tid;
        const float4* wr = (const float4*)(Wout + (size_t)o * Hc);
        const float4* hv = (const float4*)hs;
        float s = 0.f;
        for (int k = 0; k < 256; k++) {
            float4 a = hv[k], w = wr[k];
            s += a.x * w.x + a.y * w.y + a.z * w.z + a.w * w.w;
        }
        g_delta[b * Oc + o] = outt[b * Oc + o] - bout[o] - s;
    }
}

// ---------------- persistent kernel ----------------
// blocks 0..127 : gates GEMM + LSTM cell for step t       (active for t < Tc)
// blocks 128..131: y_{t-1} = (h_{t-1}@W_out.T + b_out)*m  (active for t > 0)
__global__ void __launch_bounds__(256, 1) persist_kernel(
    const float* __restrict__ x, const int* __restrict__ sl,
    const float* __restrict__ cn,
    const float* __restrict__ Wout, const float* __restrict__ bout,
    float* __restrict__ out)
{
    extern __shared__ __align__(16) ull dsm[];
    ull* sA = dsm;                    // [2][128*33] k-pairs, pitch 33 ull (264B)
    ull* sW = dsm + 2 * SA_BUF;       // [2][32*33]  k-pairs, pitch 33 ull, +(r>>4) shift
    float* gsh = (float*)dsm;         // epilogue exchange, aliases sA buf0

    __shared__ float bias_s[32];
    __shared__ int sls[Bc];

    int cb = blockIdx.x, tid = threadIdx.x;
    bool isY = (cb >= 128);

    if (tid < 128) sls[tid] = sl[tid];

    const float* wsrc; int wstride; int o0 = 0;
    if (!isY) {
        wsrc = g_W + (size_t)cb * 32 * KW; wstride = KW;
        if (tid < 32) bias_s[tid] = g_bp[cb * 32 + tid];
    } else {
        o0 = (cb - 128) * 32;
        wsrc = Wout + (size_t)o0 * Hc; wstride = Hc;
        if (tid < 32) bias_s[tid] = bout[o0 + tid];
    }

    // microtile mapping: thread covers b0..b0+3 x r0t..r0t+3
    int w = tid >> 5, l = tid & 31;
    int b0 = (w << 4) + ((l >> 3) << 2);
    int r0t = (l & 7) << 2;

    // staging mapping: (b or r) = idx>>4, k4 = idx&15  (coalesced gmem)
    int st_b = -1, st_k4 = tid & 15;   // reused per u via idx

    // cell state in registers (gate CTAs): flat = tid*4+u -> (b, jj)
    float c_reg[4];
    if (!isY) {
#pragma unroll
        for (int u = 0; u < 4; u++) {
            int flat = (tid << 2) + u;
            int b = flat >> 3, jj = flat & 7;
            c_reg[u] = cn[(size_t)b * Hc + (cb << 3) + jj];
        }
    }
    (void)st_b; (void)st_k4;
    __syncthreads();

    float4 pa[8]; float4 pw[2];

#pragma unroll 1
    for (int t = 0; t <= Tc; t++) {
        bool active = isY ? (t > 0) : (t < Tc);
        if (active) {
            int par = t & 1;
            const float* hprev = g_h + (size_t)par * (Bc * Hc);
            int NC = isY ? 16 : (t == 0 ? 20 : 18);

            // ---- prefetch chunk 0 ----
            {
                int kc = 0;
#pragma unroll
                for (int u = 0; u < 8; u++) {
                    int idx = (u << 8) + tid;
                    int b = idx >> 4, k4 = idx & 15;
                    int k = (kc << 6) + (k4 << 2);
                    pa[u] = __ldcg((const float4*)(hprev + (size_t)b * Hc + k));
                }
#pragma unroll
                for (int u = 0; u < 2; u++) {
                    int idx = (u << 8) + tid;
                    int r = idx >> 4, k4 = idx & 15;
                    pw[u] = *(const float4*)(wsrc + (size_t)r * wstride + (kc << 6) + (k4 << 2));
                }
            }

            ull acc[16];
#pragma unroll
            for (int i = 0; i < 16; i++) acc[i] = 0ull;

#pragma unroll 1
            for (int kc = 0; kc < NC; kc++) {
                int s = kc & 1;
                __syncthreads();
                // ---- store staged chunk ----
#pragma unroll
                for (int u = 0; u < 8; u++) {
                    int idx = (u << 8) + tid;
                    int b = idx >> 4, k4 = idx & 15;
                    ull* dst = sA + s * SA_BUF + b * 33 + (k4 << 1);
                    dst[0] = packf2(pa[u].x, pa[u].y);
                    dst[1] = packf2(pa[u].z, pa[u].w);
                }
#pragma unroll
                for (int u = 0; u < 2; u++) {
                    int idx = (u << 8) + tid;
                    int r = idx >> 4, k4 = idx & 15;
                    ull* dst = sW + s * SW_BUF + r * 33 + (r >> 4) + (k4 << 1);
                    dst[0] = packf2(pw[u].x, pw[u].y);
                    dst[1] = packf2(pw[u].z, pw[u].w);
                }
                // ---- prefetch next chunk ----
                if (kc + 1 < NC) {
                    int kn = kc + 1;
#pragma unroll
                    for (int u = 0; u < 8; u++) {
                        int idx = (u << 8) + tid;
                        int b = idx >> 4, k4 = idx & 15;
                        int k = (kn << 6) + (k4 << 2);
                        const float* src;
                        bool isx = false;
                        if (isY || k < 1024)  src = hprev + (size_t)b * Hc + k;
                        else if (k < 1152) {  src = x + ((size_t)b * Tc + t) * Ic + (k - 1024); isx = true; }
                        else                  src = g_delta + (size_t)b * Oc + (k - 1152);
                        float4 v = __ldcg((const float4*)src);
                        if (isx && t >= sls[b]) v = make_float4(0.f, 0.f, 0.f, 0.f);
                        pa[u] = v;
                    }
#pragma unroll
                    for (int u = 0; u < 2; u++) {
                        int idx = (u << 8) + tid;
                        int r = idx >> 4, k4 = idx & 15;
                        pw[u] = *(const float4*)(wsrc + (size_t)r * wstride + (kn << 6) + (k4 << 2));
                    }
                }
                __syncthreads();
                // ---- compute: 32 k-pairs, all addresses [base + imm] ----
                const ull* aP0 = sA + s * SA_BUF + (b0 + 0) * 33;
                const ull* aP1 = sA + s * SA_BUF + (b0 + 1) * 33;
                const ull* aP2 = sA + s * SA_BUF + (b0 + 2) * 33;
                const ull* aP3 = sA + s * SA_BUF + (b0 + 3) * 33;
                const ull* wP0 = sW + s * SW_BUF + (r0t + 0) * 33 + ((r0t + 0) >> 4);
                const ull* wP1 = sW + s * SW_BUF + (r0t + 1) * 33 + ((r0t + 1) >> 4);
                const ull* wP2 = sW + s * SW_BUF + (r0t + 2) * 33 + ((r0t + 2) >> 4);
                const ull* wP3 = sW + s * SW_BUF + (r0t + 3) * 33 + ((r0t + 3) >> 4);
#pragma unroll 8
                for (int kp = 0; kp < 32; kp++) {
                    ull a0 = aP0[kp], a1 = aP1[kp], a2v = aP2[kp], a3v = aP3[kp];
                    ull w0 = wP0[kp], w1 = wP1[kp], w2v = wP2[kp], w3v = wP3[kp];
                    ffma2(acc[0],  a0,  w0); ffma2(acc[1],  a0,  w1);
                    ffma2(acc[2],  a0,  w2v); ffma2(acc[3],  a0,  w3v);
                    ffma2(acc[4],  a1,  w0); ffma2(acc[5],  a1,  w1);
                    ffma2(acc[6],  a1,  w2v); ffma2(acc[7],  a1,  w3v);
                    ffma2(acc[8],  a2v, w0); ffma2(acc[9],  a2v, w1);
                    ffma2(acc[10], a2v, w2v); ffma2(acc[11], a2v, w3v);
                    ffma2(acc[12], a3v, w0); ffma2(acc[13], a3v, w1);
                    ffma2(acc[14], a3v, w2v); ffma2(acc[15], a3v, w3v);
                }
            }

            if (isY) {
#pragma unroll
                for (int bi = 0; bi < 4; bi++)
#pragma unroll
                    for (int ri = 0; ri < 4; ri++) {
                        float2 p = asf2(acc[bi * 4 + ri]);
                        float val = p.x + p.y + bias_s[r0t + ri];
                        int b = b0 + bi, o = o0 + r0t + ri;
                        float m = ((t - 1) < sls[b]) ? 1.0f : 0.0f;
                        __stcg(&out[((size_t)b * Tc + (t - 1)) * Oc + o], val * m);
                    }
            } else {
                // exchange gates through smem, then registered cell update
#pragma unroll
                for (int bi = 0; bi < 4; bi++)
#pragma unroll
                    for (int ri = 0; ri < 4; ri++) {
                        float2 p = asf2(acc[bi * 4 + ri]);
                        gsh[(b0 + bi) * 33 + r0t + ri] = p.x + p.y + bias_s[r0t + ri];
                    }
                __syncthreads();

                int nxt = par ^ 1;
                float* hdst = g_h + (size_t)nxt * (Bc * Hc);
#pragma unroll
                for (int u = 0; u < 4; u++) {
                    int flat = (tid << 2) + u;
                    int b = flat >> 3, jj = flat & 7;
                    float ig = sigm(gsh[b * 33 + jj]);
                    float fg = sigm(gsh[b * 33 + 8 + jj]);
                    float gg = tanhf(gsh[b * 33 + 16 + jj]);
                    float og = sigm(gsh[b * 33 + 24 + jj]);
                    float c = fg * c_reg[u] + ig * gg;
                    c_reg[u] = c;
                    __stcg(&hdst[(size_t)b * Hc + (cb << 3) + jj], og * tanhf(c));
                }
            }
        }
        grid_sync();
    }
}

// ---------------- launch: 3 graph nodes ----------------
extern "C" void kernel_launch(void* const* d_in, const int* in_sizes, int n_in,
                              void* d_out, int out_size) {
    const float* x    = (const float*)d_in[0];
    const int*   sl   = (const int*)  d_in[1];
    const float* hn   = (const float*)d_in[2];
    const float* cn   = (const float*)d_in[3];
    const float* outt = (const float*)d_in[4];
    const float* Wih  = (const float*)d_in[5];
    const float* Whh  = (const float*)d_in[6];
    const float* bih  = (const float*)d_in[7];
    const float* bhh  = (const float*)d_in[8];
    const float* Wout = (const float*)d_in[9];
    const float* bout = (const float*)d_in[10];
    float* out = (float*)d_out;

    cudaFuncSetAttribute(persist_kernel,
                         cudaFuncAttributeMaxDynamicSharedMemorySize, SMEM_BYTES);
    pack_weights<<<128, 256>>>(Wih, Whh, bih, bhh, Wout, bout);
    delta_init<<<128, 256>>>(hn, outt, Wout, bout);
    persist_kernel<<<NBLK, 256, SMEM_BYTES>>>(x, sl, cn, Wout, bout, out);
}

// round 7
// speedup vs baseline: 5.5767x; 5.5767x over previous
#include <cuda_runtime.h>
#include <cuda_bf16.h>
#include <math.h>
#include <stdint.h>

#define Bc 128
#define Tc 1024
#define Ic 128
#define Hc 1024
#define KW 1280        // packed K in g_W: 1024 W_eff + 128 W_x + 128 W_o
#define NBLK 132       // 128 gate CTAs + 4 y CTAs

// smem: resident W planes then A double buffers
#define SM_A 147456                      // 2 planes * 32 rows * 2304 B
#define SMEM_BYTES (SM_A + 2*32768)      // 212992

typedef unsigned long long ull;

// ---------------- device scratch (static) ----------------
__device__ float g_W[(size_t)4096 * KW];                 // packed, grouped by cb: row = cb*32+n
__device__ float g_bp[4096];                             // grouped bias
__device__ float g_delta[Bc * 128];
__device__ float g_g0[(size_t)Bc * 4096];                // t=0 gate correction, grouped
// pre-swizzled bf16 planes
__device__ __align__(16) unsigned char g_hsp[2 * 2 * 16 * 16384];               // [par][plane][chunk][16KB]
__device__ __align__(16) unsigned char g_xsp[(size_t)Tc * 2 * 2 * 16384];       // [t][plane][chunk][16KB]
__device__ __align__(16) unsigned char g_Wsp[(size_t)128 * 147456];             // [cb][plane][32][2304]
__device__ __align__(16) unsigned char g_Wosp[(size_t)4 * 147456];              // [cy][plane][32][2304]

__device__ unsigned g_cnt = 0;
__device__ volatile unsigned g_gen = 0;

// ---------------- helpers ----------------
__device__ __forceinline__ uint32_t swz(uint32_t b) { return b ^ ((b >> 3) & 0x70); }
__device__ __forceinline__ uint32_t s2u(const void* p) { return (uint32_t)__cvta_generic_to_shared(p); }
__device__ __forceinline__ float sigm(float v) { return 1.0f / (1.0f + expf(-v)); }
__device__ __forceinline__ unsigned short bfu(__nv_bfloat16 h) { return *(unsigned short*)&h; }

__device__ __forceinline__ void grid_sync() {
    __syncthreads();
    if (threadIdx.x == 0) {
        __threadfence();
        unsigned my = g_gen;
        if (atomicAdd(&g_cnt, 1) == NBLK - 1) {
            g_cnt = 0;
            __threadfence();
            g_gen = my + 1;
        } else {
            while (g_gen == my) { }
        }
        __threadfence();
    }
    __syncthreads();
}

__device__ __forceinline__ void ldm_x4(uint32_t* r, uint32_t a) {
    asm volatile("ldmatrix.sync.aligned.m8n8.x4.shared.b16 {%0,%1,%2,%3}, [%4];"
                 : "=r"(r[0]), "=r"(r[1]), "=r"(r[2]), "=r"(r[3]) : "r"(a));
}
__device__ __forceinline__ void ldm_x2(uint32_t* r, uint32_t a) {
    asm volatile("ldmatrix.sync.aligned.m8n8.x2.shared.b16 {%0,%1}, [%2];"
                 : "=r"(r[0]), "=r"(r[1]) : "r"(a));
}
__device__ __forceinline__ void mma16816(float* d, const uint32_t* a, const uint32_t* b) {
    asm volatile("mma.sync.aligned.m16n8k16.row.col.f32.bf16.bf16.f32 "
                 "{%0,%1,%2,%3}, {%4,%5,%6,%7}, {%8,%9}, {%0,%1,%2,%3};"
                 : "+f"(d[0]), "+f"(d[1]), "+f"(d[2]), "+f"(d[3])
                 : "r"(a[0]), "r"(a[1]), "r"(a[2]), "r"(a[3]), "r"(b[0]), "r"(b[1]));
}

#define CP16(dst, src) asm volatile("cp.async.cg.shared.global [%0], [%1], 16;" :: "r"(dst), "l"(src))
#define CPCOMMIT() asm volatile("cp.async.commit_group;")
#define CPWAIT(n)  asm volatile("cp.async.wait_group %0;" :: "n"(n))

// ---------------- prologue: pack effective weights (grouped) ----------------
__global__ void __launch_bounds__(256, 1) pack_weights(
    const float* __restrict__ Wih, const float* __restrict__ Whh,
    const float* __restrict__ bih, const float* __restrict__ bhh,
    const float* __restrict__ Wout, const float* __restrict__ bout)
{
    __shared__ float ao[32][129];
    __shared__ float wos[128][33];
    int cb = blockIdx.x, tid = threadIdx.x;

    for (int i = 0; i < 4; i++) {
        int idx = i * 256 + tid;
        int r = idx >> 5, c4 = idx & 31;
        int gr = ((r >> 3) << 10) + (cb << 3) + (r & 7);
        float4 v = *(const float4*)(Wih + (size_t)gr * 256 + 128 + (c4 << 2));
        ao[r][(c4 << 2) + 0] = v.x; ao[r][(c4 << 2) + 1] = v.y;
        ao[r][(c4 << 2) + 2] = v.z; ao[r][(c4 << 2) + 3] = v.w;
    }
    __syncthreads();

    int r = tid >> 3;
    int gr = ((r >> 3) << 10) + (cb << 3) + (r & 7);
    int kk0 = (tid & 7) << 2;
    for (int kc = 0; kc < 32; kc++) {
        for (int i = 0; i < 4; i++) {
            int idx = i * 256 + tid;
            int o = idx >> 3, c4 = idx & 7;
            float4 v = *(const float4*)(Wout + (size_t)o * Hc + (kc << 5) + (c4 << 2));
            wos[o][(c4 << 2) + 0] = v.x; wos[o][(c4 << 2) + 1] = v.y;
            wos[o][(c4 << 2) + 2] = v.z; wos[o][(c4 << 2) + 3] = v.w;
        }
        __syncthreads();
        float a0 = 0.f, a1 = 0.f, a2 = 0.f, a3 = 0.f;
#pragma unroll 4
        for (int o = 0; o < 128; o++) {
            float a = ao[r][o];
            a0 += a * wos[o][kk0 + 0]; a1 += a * wos[o][kk0 + 1];
            a2 += a * wos[o][kk0 + 2]; a3 += a * wos[o][kk0 + 3];
        }
        int k = (kc << 5) + kk0;
        const float* hh = Whh + (size_t)gr * Hc + k;
        float* dst = g_W + (size_t)(cb * 32 + r) * KW + k;
        dst[0] = hh[0] + a0; dst[1] = hh[1] + a1;
        dst[2] = hh[2] + a2; dst[3] = hh[3] + a3;
        __syncthreads();
    }
    for (int i = 0; i < 8; i++) {
        int idx = i * 256 + tid;
        int rr = idx >> 6, c4 = idx & 63;
        int grr = ((rr >> 3) << 10) + (cb << 3) + (rr & 7);
        float4 v = *(const float4*)(Wih + (size_t)grr * 256 + (c4 << 2));
        *(float4*)(g_W + (size_t)(cb * 32 + rr) * KW + 1024 + (c4 << 2)) = v;
    }
    if (tid < 32) {
        int grr = ((tid >> 3) << 10) + (cb << 3) + (tid & 7);
        float s = bih[grr] + bhh[grr];
        for (int o = 0; o < 128; o++) s += ao[tid][o] * bout[o];
        g_bp[cb * 32 + tid] = s;
    }
}

// ---------------- prologue: delta ----------------
__global__ void __launch_bounds__(256, 1) delta_init(
    const float* __restrict__ hn, const float* __restrict__ outt,
    const float* __restrict__ Wout, const float* __restrict__ bout)
{
    __shared__ __align__(16) float hs[Hc];
    int b = blockIdx.x, tid = threadIdx.x;
    for (int k = tid; k < Hc; k += 256) hs[k] = hn[(size_t)b * Hc + k];
    __syncthreads();
    if (tid < 128) {
        int o = tid;
        const float4* wr = (const float4*)(Wout + (size_t)o * Hc);
        const float4* hv = (const float4*)hs;
        float s = 0.f;
        for (int k = 0; k < 256; k++) {
            float4 a = hv[k], w = wr[k];
            s += a.x * w.x + a.y * w.y + a.z * w.z + a.w * w.w;
        }
        g_delta[b * 128 + o] = outt[b * 128 + o] - bout[o] - s;
    }
}

// ---------------- prologue: g0 = delta @ W_o^T (grouped) ----------------
__global__ void __launch_bounds__(256, 1) g0_init()
{
    __shared__ float ws[32][132];
    int cb = blockIdx.x, tid = threadIdx.x;
    for (int i = tid; i < 32 * 128; i += 256) {
        int n = i >> 7, o = i & 127;
        ws[n][o] = g_W[(size_t)(cb * 32 + n) * KW + 1152 + o];
    }
    __syncthreads();
    int b = tid >> 1, nh = (tid & 1) * 16;
    float acc[16];
#pragma unroll
    for (int n = 0; n < 16; n++) acc[n] = 0.f;
    for (int o = 0; o < 128; o++) {
        float dv = g_delta[b * 128 + o];
#pragma unroll
        for (int n = 0; n < 16; n++) acc[n] += dv * ws[nh + n][o];
    }
    for (int n = 0; n < 16; n++)
        g_g0[(size_t)b * 4096 + cb * 32 + nh + n] = acc[n];
}

// ---------------- prologue: split weights to bf16 planes (smem layout) ----------------
__global__ void __launch_bounds__(256, 1) split_w(const float* __restrict__ Wout)
{
    int bx = blockIdx.x, tid = threadIdx.x;
    if (bx < 128) {
        int cb = bx;
        for (int i = tid; i < 32 * 1152; i += 256) {
            int n = i / 1152, k = i % 1152;
            float v = g_W[(size_t)(cb * 32 + n) * KW + k];
            __nv_bfloat16 hi = __float2bfloat16(v);
            __nv_bfloat16 lo = __float2bfloat16(v - __bfloat162float(hi));
            uint32_t off = (uint32_t)(n * 2304) + (((uint32_t)(k * 2)) ^ ((n & 7) << 4));
            unsigned char* base = g_Wsp + (size_t)cb * 147456;
            *(__nv_bfloat16*)(base + off) = hi;
            *(__nv_bfloat16*)(base + 73728 + off) = lo;
        }
    } else {
        int cy = bx - 128;
        for (int i = tid; i < 32 * 1024; i += 256) {
            int n = i >> 10, k = i & 1023;
            float v = Wout[(size_t)(cy * 32 + n) * Hc + k];
            __nv_bfloat16 hi = __float2bfloat16(v);
            __nv_bfloat16 lo = __float2bfloat16(v - __bfloat162float(hi));
            uint32_t off = (uint32_t)(n * 2304) + (((uint32_t)(k * 2)) ^ ((n & 7) << 4));
            unsigned char* base = g_Wosp + (size_t)cy * 147456;
            *(__nv_bfloat16*)(base + off) = hi;
            *(__nv_bfloat16*)(base + 73728 + off) = lo;
        }
    }
}

// ---------------- prologue: split x (masked) ----------------
__global__ void __launch_bounds__(256, 1) split_x(
    const float* __restrict__ x, const int* __restrict__ sl)
{
    int t = blockIdx.x, tid = threadIdx.x;
    for (int idx = tid; idx < 16384; idx += 256) {
        int b = idx >> 7, kk = idx & 127;
        float v = (t < sl[b]) ? x[((size_t)b * Tc + t) * Ic + kk] : 0.0f;
        __nv_bfloat16 hi = __float2bfloat16(v);
        __nv_bfloat16 lo = __float2bfloat16(v - __bfloat162float(hi));
        int kg = kk >> 6;
        uint32_t off = swz((uint32_t)(b * 128 + (kk & 63) * 2));
        *(__nv_bfloat16*)(g_xsp + (((size_t)t * 2 + 0) * 2 + kg) * 16384 + off) = hi;
        *(__nv_bfloat16*)(g_xsp + (((size_t)t * 2 + 1) * 2 + kg) * 16384 + off) = lo;
    }
}

// ---------------- prologue: split hn into g_hsp[0] ----------------
__global__ void __launch_bounds__(256, 1) split_h0(const float* __restrict__ hn)
{
    int b = blockIdx.x, tid = threadIdx.x;
    for (int kk = tid; kk < 1024; kk += 256) {
        float v = hn[(size_t)b * Hc + kk];
        __nv_bfloat16 hi = __float2bfloat16(v);
        __nv_bfloat16 lo = __float2bfloat16(v - __bfloat162float(hi));
        int kg = kk >> 6;
        uint32_t off = swz((uint32_t)(b * 128 + (kk & 63) * 2));
        *(__nv_bfloat16*)(g_hsp + ((size_t)(0 * 2 + 0) * 16 + kg) * 16384 + off) = hi;
        *(__nv_bfloat16*)(g_hsp + ((size_t)(0 * 2 + 1) * 16 + kg) * 16384 + off) = lo;
    }
}

// ---------------- persistent mma.sync kernel ----------------
__global__ void __launch_bounds__(256, 1) persist_kernel(
    const int* __restrict__ sl, const float* __restrict__ cn,
    const float* __restrict__ bout, float* __restrict__ out)
{
    extern __shared__ unsigned char smc[];
    const uint32_t sWu = s2u(smc);
    const uint32_t sAu = sWu + SM_A;
    __shared__ float bias_s[32];
    __shared__ int sls[128];

    int cb = blockIdx.x, tid = threadIdx.x;
    int lane = tid & 31, wid = tid >> 5;
    bool isY = (cb >= 128);
    int cy = cb - 128;
    int mrow = (wid >> 1) << 5;      // warp m origin (0,32,64,96)
    int ncol = (wid & 1) << 4;       // warp n origin (0,16)

    if (tid < 128) sls[tid] = sl[tid];
    if (tid < 32) bias_s[tid] = isY ? bout[cy * 32 + tid] : g_bp[cb * 32 + tid];

    // load resident W planes (147456 B)
    {
        const uint4* ws4 = (const uint4*)(isY ? (g_Wosp + (size_t)cy * 147456)
                                              : (g_Wsp + (size_t)cb * 147456));
        uint4* wd4 = (uint4*)smc;
#pragma unroll
        for (int i = 0; i < 36; i++) wd4[i * 256 + tid] = ws4[i * 256 + tid];
    }

    // ldmatrix address precompute
    uint32_t aB0 = sAu + (uint32_t)((mrow + (lane & 15)) * 128);
    uint32_t aB1 = aB0 + 16 * 128;
    uint32_t ax = (((uint32_t)lane >> 4) << 4) ^ (((uint32_t)lane & 7) << 4);
    uint32_t bn = (uint32_t)(ncol + (lane & 7));
    uint32_t bB0 = sWu + bn * 2304;
    uint32_t bB1 = bB0 + 8 * 2304;
    uint32_t bx = ((((uint32_t)lane >> 3) & 1) << 4) ^ (((uint32_t)lane & 7) << 4);

    // cell state in registers
    float c_reg[4];
    if (!isY) {
#pragma unroll
        for (int v = 0; v < 2; v++) {
            int q = tid * 2 + v;
            int b = q >> 2, jp = (q & 3) << 1;
            c_reg[v * 2 + 0] = cn[(size_t)b * Hc + cb * 8 + jp];
            c_reg[v * 2 + 1] = cn[(size_t)b * Hc + cb * 8 + jp + 1];
        }
    }
    __syncthreads();

    const int NC = isY ? 16 : 18;

#pragma unroll 1
    for (int t = 0; t <= Tc; t++) {
        bool active = isY ? (t > 0) : (t < Tc);
        if (active) {
            int par = t & 1;

            auto stage = [&](int c) {
#pragma unroll
                for (int p = 0; p < 2; p++) {
                    const unsigned char* src;
                    if (!isY && c >= 16)
                        src = g_xsp + (((size_t)t * 2 + p) * 2 + (c - 16)) * 16384;
                    else
                        src = g_hsp + (((size_t)par * 2 + p) * 16 + c) * 16384;
                    uint32_t dst = sAu + (uint32_t)((c & 1) * 32768 + p * 16384 + tid * 16);
                    const unsigned char* s = src + tid * 16;
#pragma unroll
                    for (int i = 0; i < 4; i++)
                        CP16(dst + i * 4096, s + i * 4096);
                }
            };

            stage(0);
            CPCOMMIT();

            float d00[4], d01[4], d10[4], d11[4];
#pragma unroll
            for (int i = 0; i < 4; i++) { d00[i] = 0.f; d01[i] = 0.f; d10[i] = 0.f; d11[i] = 0.f; }

#pragma unroll 1
            for (int c = 0; c < NC; c++) {
                if (c + 1 < NC) { stage(c + 1); CPCOMMIT(); CPWAIT(1); }
                else            { CPWAIT(0); }
                __syncthreads();
                uint32_t sOff = (uint32_t)((c & 1) * 32768);
                uint32_t kbase = (uint32_t)(c * 128);
#pragma unroll
                for (int kt = 0; kt < 4; kt++) {
                    uint32_t ko = ((uint32_t)(kt * 32)) ^ ax;
                    uint32_t kb = kbase + (((uint32_t)(kt * 32)) ^ bx);
                    uint32_t Ah0[4], Ah1[4], Al0[4], Al1[4], Bh0[2], Bh1[2], Bl0[2], Bl1[2];
                    ldm_x4(Ah0, aB0 + sOff + ko);
                    ldm_x4(Ah1, aB1 + sOff + ko);
                    ldm_x4(Al0, aB0 + sOff + 16384 + ko);
                    ldm_x4(Al1, aB1 + sOff + 16384 + ko);
                    ldm_x2(Bh0, bB0 + kb);
                    ldm_x2(Bh1, bB1 + kb);
                    ldm_x2(Bl0, bB0 + 73728 + kb);
                    ldm_x2(Bl1, bB1 + 73728 + kb);
                    mma16816(d00, Ah0, Bh0); mma16816(d01, Ah0, Bh1);
                    mma16816(d10, Ah1, Bh0); mma16816(d11, Ah1, Bh1);
                    mma16816(d00, Al0, Bh0); mma16816(d01, Al0, Bh1);
                    mma16816(d10, Al1, Bh0); mma16816(d11, Al1, Bh1);
                    mma16816(d00, Ah0, Bl0); mma16816(d01, Ah0, Bl1);
                    mma16816(d10, Ah1, Bl0); mma16816(d11, Ah1, Bl1);
                }
                __syncthreads();
            }

            if (!isY) {
                // gate epilogue: exchange via smem (aliases A buf0, safe post-sync)
                float* gsh = (float*)(smc + SM_A);
                int mfr = mrow + (lane >> 2);
                int nfr = ncol + ((lane & 3) << 1);
                float* dp[4] = { d00, d01, d10, d11 };
#pragma unroll
                for (int mt = 0; mt < 2; mt++)
#pragma unroll
                    for (int nt = 0; nt < 2; nt++) {
                        float* dd = dp[mt * 2 + nt];
                        int m0 = mfr + mt * 16;
                        int n0 = nfr + nt * 8;
                        gsh[m0 * 33 + n0]           = dd[0] + bias_s[n0];
                        gsh[m0 * 33 + n0 + 1]       = dd[1] + bias_s[n0 + 1];
                        gsh[(m0 + 8) * 33 + n0]     = dd[2] + bias_s[n0];
                        gsh[(m0 + 8) * 33 + n0 + 1] = dd[3] + bias_s[n0 + 1];
                    }
                __syncthreads();

                int nxt = par ^ 1;
#pragma unroll
                for (int v = 0; v < 2; v++) {
                    int q = tid * 2 + v;
                    int b = q >> 2, jp = (q & 3) << 1;
                    float hv[2];
#pragma unroll
                    for (int w2 = 0; w2 < 2; w2++) {
                        int jj = jp + w2;
                        float gi = gsh[b * 33 + jj];
                        float gf = gsh[b * 33 + 8 + jj];
                        float gg = gsh[b * 33 + 16 + jj];
                        float go = gsh[b * 33 + 24 + jj];
                        if (t == 0) {
                            const float* g0 = g_g0 + (size_t)b * 4096 + cb * 32;
                            gi += g0[jj]; gf += g0[8 + jj]; gg += g0[16 + jj]; go += g0[24 + jj];
                        }
                        float cc = sigm(gf) * c_reg[v * 2 + w2] + sigm(gi) * tanhf(gg);
                        c_reg[v * 2 + w2] = cc;
                        hv[w2] = sigm(go) * tanhf(cc);
                    }
                    int j0 = cb * 8 + jp;
                    int ch = j0 >> 6, kin = j0 & 63;
                    uint32_t off = swz((uint32_t)(b * 128 + kin * 2));
                    __nv_bfloat16 h0 = __float2bfloat16(hv[0]);
                    __nv_bfloat16 h1 = __float2bfloat16(hv[1]);
                    __nv_bfloat16 l0 = __float2bfloat16(hv[0] - __bfloat162float(h0));
                    __nv_bfloat16 l1 = __float2bfloat16(hv[1] - __bfloat162float(h1));
                    unsigned int hi2 = ((unsigned int)bfu(h1) << 16) | bfu(h0);
                    unsigned int lo2 = ((unsigned int)bfu(l1) << 16) | bfu(l0);
                    __stcg((unsigned int*)(g_hsp + (((size_t)nxt * 2 + 0) * 16 + ch) * 16384 + off), hi2);
                    __stcg((unsigned int*)(g_hsp + (((size_t)nxt * 2 + 1) * 16 + ch) * 16384 + off), lo2);
                }
            } else {
                // y epilogue: direct store with mask
                int tt = t - 1;
                int mfr = mrow + (lane >> 2);
                int nfr = ncol + ((lane & 3) << 1);
                float* dp[4] = { d00, d01, d10, d11 };
#pragma unroll
                for (int mt = 0; mt < 2; mt++)
#pragma unroll
                    for (int nt = 0; nt < 2; nt++) {
                        float* dd = dp[mt * 2 + nt];
                        int b0r = mfr + mt * 16;
                        int n0 = nfr + nt * 8;
                        float mk0 = (tt < sls[b0r]) ? 1.0f : 0.0f;
                        float mk1 = (tt < sls[b0r + 8]) ? 1.0f : 0.0f;
                        float2 v0, v1;
                        v0.x = (dd[0] + bias_s[n0]) * mk0;
                        v0.y = (dd[1] + bias_s[n0 + 1]) * mk0;
                        v1.x = (dd[2] + bias_s[n0]) * mk1;
                        v1.y = (dd[3] + bias_s[n0 + 1]) * mk1;
                        *(float2*)(out + ((size_t)b0r * Tc + tt) * 128 + cy * 32 + n0) = v0;
                        *(float2*)(out + ((size_t)(b0r + 8) * Tc + tt) * 128 + cy * 32 + n0) = v1;
                    }
            }
        }
        grid_sync();
    }
}

// ---------------- launch ----------------
extern "C" void kernel_launch(void* const* d_in, const int* in_sizes, int n_in,
                              void* d_out, int out_size) {
    const float* x    = (const float*)d_in[0];
    const int*   sl   = (const int*)  d_in[1];
    const float* hn   = (const float*)d_in[2];
    const float* cn   = (const float*)d_in[3];
    const float* outt = (const float*)d_in[4];
    const float* Wih  = (const float*)d_in[5];
    const float* Whh  = (const float*)d_in[6];
    const float* bih  = (const float*)d_in[7];
    const float* bhh  = (const float*)d_in[8];
    const float* Wout = (const float*)d_in[9];
    const float* bout = (const float*)d_in[10];
    float* out = (float*)d_out;

    cudaFuncSetAttribute(persist_kernel,
                         cudaFuncAttributeMaxDynamicSharedMemorySize, SMEM_BYTES);
    pack_weights<<<128, 256>>>(Wih, Whh, bih, bhh, Wout, bout);
    delta_init<<<128, 256>>>(hn, outt, Wout, bout);
    g0_init<<<128, 256>>>();
    split_w<<<132, 256>>>(Wout);
    split_x<<<1024, 256>>>(x, sl);
    split_h0<<<128, 256>>>(hn);
    persist_kernel<<<NBLK, 256, SMEM_BYTES>>>(sl, cn, bout, out);
}

// round 8
// speedup vs baseline: 6.3459x; 1.1379x over previous
#include <cuda_runtime.h>
#include <cuda_fp16.h>
#include <math.h>
#include <stdint.h>

#define Bc 128
#define Tc 1024
#define Ic 128
#define Hc 1024
#define KW 1280        // packed K in g_W: 1024 W_eff + 128 W_x + 128 W_o
#define NBLK 132       // 128 gate CTAs + 4 y CTAs

// smem: resident W (fp16, 1 plane) then 4 A buffers (32KB each)
#define SM_A 73728
#define SMEM_BYTES (SM_A + 4*32768)      // 204800

typedef unsigned long long ull;

// ---------------- device scratch (static) ----------------
__device__ float g_W[(size_t)4096 * KW];                 // packed fp32, grouped: row = cb*32+n
__device__ float g_bp[4096];
__device__ float g_delta[Bc * 128];
__device__ float g_g0[(size_t)Bc * 4096];                // t=0 gate correction, grouped
// pre-swizzled fp16 planes
__device__ __align__(16) unsigned char g_hsp[2 * 2 * 16 * 16384];           // [par][plane][chunk][16KB]
__device__ __align__(16) unsigned char g_xsp[(size_t)Tc * 2 * 2 * 16384];   // [t][plane][chunk][16KB]
__device__ __align__(16) unsigned char g_Wsp[(size_t)128 * 73728];          // [cb][32][2304]
__device__ __align__(16) unsigned char g_Wosp[(size_t)4 * 73728];           // [cy][32][2304]

__device__ unsigned g_cnt = 0;
__device__ volatile unsigned g_gen = 0;

// ---------------- helpers ----------------
__device__ __forceinline__ uint32_t swz(uint32_t b) { return b ^ ((b >> 3) & 0x70); }
__device__ __forceinline__ uint32_t s2u(const void* p) { return (uint32_t)__cvta_generic_to_shared(p); }
__device__ __forceinline__ float sigm(float v) { return 1.0f / (1.0f + expf(-v)); }
__device__ __forceinline__ unsigned short hfu(__half h) { return *(unsigned short*)&h; }

__device__ __forceinline__ void grid_sync() {
    __syncthreads();
    if (threadIdx.x == 0) {
        __threadfence();
        unsigned my = g_gen;
        if (atomicAdd(&g_cnt, 1) == NBLK - 1) {
            g_cnt = 0;
            __threadfence();
            g_gen = my + 1;
        } else {
            while (g_gen == my) { }
        }
        __threadfence();
    }
    __syncthreads();
}

__device__ __forceinline__ void ldm_x4(uint32_t* r, uint32_t a) {
    asm volatile("ldmatrix.sync.aligned.m8n8.x4.shared.b16 {%0,%1,%2,%3}, [%4];"
                 : "=r"(r[0]), "=r"(r[1]), "=r"(r[2]), "=r"(r[3]) : "r"(a));
}
__device__ __forceinline__ void ldm_x2(uint32_t* r, uint32_t a) {
    asm volatile("ldmatrix.sync.aligned.m8n8.x2.shared.b16 {%0,%1}, [%2];"
                 : "=r"(r[0]), "=r"(r[1]) : "r"(a));
}
__device__ __forceinline__ void mma16816(float* d, const uint32_t* a, const uint32_t* b) {
    asm volatile("mma.sync.aligned.m16n8k16.row.col.f32.f16.f16.f32 "
                 "{%0,%1,%2,%3}, {%4,%5,%6,%7}, {%8,%9}, {%0,%1,%2,%3};"
                 : "+f"(d[0]), "+f"(d[1]), "+f"(d[2]), "+f"(d[3])
                 : "r"(a[0]), "r"(a[1]), "r"(a[2]), "r"(a[3]), "r"(b[0]), "r"(b[1]));
}

#define CP16(dst, src) asm volatile("cp.async.cg.shared.global [%0], [%1], 16;" :: "r"(dst), "l"(src))
#define CPCOMMIT() asm volatile("cp.async.commit_group;")
#define CPWAIT(n)  asm volatile("cp.async.wait_group %0;" :: "n"(n))

// ---------------- prologue: pack effective weights (grouped) ----------------
__global__ void __launch_bounds__(256, 1) pack_weights(
    const float* __restrict__ Wih, const float* __restrict__ Whh,
    const float* __restrict__ bih, const float* __restrict__ bhh,
    const float* __restrict__ Wout, const float* __restrict__ bout)
{
    __shared__ float ao[32][129];
    __shared__ float wos[128][33];
    int cb = blockIdx.x, tid = threadIdx.x;

    for (int i = 0; i < 4; i++) {
        int idx = i * 256 + tid;
        int r = idx >> 5, c4 = idx & 31;
        int gr = ((r >> 3) << 10) + (cb << 3) + (r & 7);
        float4 v = *(const float4*)(Wih + (size_t)gr * 256 + 128 + (c4 << 2));
        ao[r][(c4 << 2) + 0] = v.x; ao[r][(c4 << 2) + 1] = v.y;
        ao[r][(c4 << 2) + 2] = v.z; ao[r][(c4 << 2) + 3] = v.w;
    }
    __syncthreads();

    int r = tid >> 3;
    int gr = ((r >> 3) << 10) + (cb << 3) + (r & 7);
    int kk0 = (tid & 7) << 2;
    for (int kc = 0; kc < 32; kc++) {
        for (int i = 0; i < 4; i++) {
            int idx = i * 256 + tid;
            int o = idx >> 3, c4 = idx & 7;
            float4 v = *(const float4*)(Wout + (size_t)o * Hc + (kc << 5) + (c4 << 2));
            wos[o][(c4 << 2) + 0] = v.x; wos[o][(c4 << 2) + 1] = v.y;
            wos[o][(c4 << 2) + 2] = v.z; wos[o][(c4 << 2) + 3] = v.w;
        }
        __syncthreads();
        float a0 = 0.f, a1 = 0.f, a2 = 0.f, a3 = 0.f;
#pragma unroll 4
        for (int o = 0; o < 128; o++) {
            float a = ao[r][o];
            a0 += a * wos[o][kk0 + 0]; a1 += a * wos[o][kk0 + 1];
            a2 += a * wos[o][kk0 + 2]; a3 += a * wos[o][kk0 + 3];
        }
        int k = (kc << 5) + kk0;
        const float* hh = Whh + (size_t)gr * Hc + k;
        float* dst = g_W + (size_t)(cb * 32 + r) * KW + k;
        dst[0] = hh[0] + a0; dst[1] = hh[1] + a1;
        dst[2] = hh[2] + a2; dst[3] = hh[3] + a3;
        __syncthreads();
    }
    for (int i = 0; i < 8; i++) {
        int idx = i * 256 + tid;
        int rr = idx >> 6, c4 = idx & 63;
        int grr = ((rr >> 3) << 10) + (cb << 3) + (rr & 7);
        float4 v = *(const float4*)(Wih + (size_t)grr * 256 + (c4 << 2));
        *(float4*)(g_W + (size_t)(cb * 32 + rr) * KW + 1024 + (c4 << 2)) = v;
    }
    if (tid < 32) {
        int grr = ((tid >> 3) << 10) + (cb << 3) + (tid & 7);
        float s = bih[grr] + bhh[grr];
        for (int o = 0; o < 128; o++) s += ao[tid][o] * bout[o];
        g_bp[cb * 32 + tid] = s;
    }
}

// ---------------- prologue: delta ----------------
__global__ void __launch_bounds__(256, 1) delta_init(
    const float* __restrict__ hn, const float* __restrict__ outt,
    const float* __restrict__ Wout, const float* __restrict__ bout)
{
    __shared__ __align__(16) float hs[Hc];
    int b = blockIdx.x, tid = threadIdx.x;
    for (int k = tid; k < Hc; k += 256) hs[k] = hn[(size_t)b * Hc + k];
    __syncthreads();
    if (tid < 128) {
        int o = tid;
        const float4* wr = (const float4*)(Wout + (size_t)o * Hc);
        const float4* hv = (const float4*)hs;
        float s = 0.f;
        for (int k = 0; k < 256; k++) {
            float4 a = hv[k], w = wr[k];
            s += a.x * w.x + a.y * w.y + a.z * w.z + a.w * w.w;
        }
        g_delta[b * 128 + o] = outt[b * 128 + o] - bout[o] - s;
    }
}

// ---------------- prologue: g0 = delta @ W_o^T (grouped) ----------------
__global__ void __launch_bounds__(256, 1) g0_init()
{
    __shared__ float ws[32][132];
    int cb = blockIdx.x, tid = threadIdx.x;
    for (int i = tid; i < 32 * 128; i += 256) {
        int n = i >> 7, o = i & 127;
        ws[n][o] = g_W[(size_t)(cb * 32 + n) * KW + 1152 + o];
    }
    __syncthreads();
    int b = tid >> 1, nh = (tid & 1) * 16;
    float acc[16];
#pragma unroll
    for (int n = 0; n < 16; n++) acc[n] = 0.f;
    for (int o = 0; o < 128; o++) {
        float dv = g_delta[b * 128 + o];
#pragma unroll
        for (int n = 0; n < 16; n++) acc[n] += dv * ws[nh + n][o];
    }
    for (int n = 0; n < 16; n++)
        g_g0[(size_t)b * 4096 + cb * 32 + nh + n] = acc[n];
}

// ---------------- prologue: split weights to single fp16 plane ----------------
__global__ void __launch_bounds__(256, 1) split_w(const float* __restrict__ Wout)
{
    int bx = blockIdx.x, tid = threadIdx.x;
    if (bx < 128) {
        int cb = bx;
        for (int i = tid; i < 32 * 1152; i += 256) {
            int n = i / 1152, k = i % 1152;
            float v = g_W[(size_t)(cb * 32 + n) * KW + k];
            uint32_t off = (uint32_t)(n * 2304) + (((uint32_t)(k * 2)) ^ ((n & 7) << 4));
            *(__half*)(g_Wsp + (size_t)cb * 73728 + off) = __float2half(v);
        }
    } else {
        int cy = bx - 128;
        for (int i = tid; i < 32 * 1024; i += 256) {
            int n = i >> 10, k = i & 1023;
            float v = Wout[(size_t)(cy * 32 + n) * Hc + k];
            uint32_t off = (uint32_t)(n * 2304) + (((uint32_t)(k * 2)) ^ ((n & 7) << 4));
            *(__half*)(g_Wosp + (size_t)cy * 73728 + off) = __float2half(v);
        }
    }
}

// ---------------- prologue: split x (masked) to fp16 hi/lo planes ----------------
__global__ void __launch_bounds__(256, 1) split_x(
    const float* __restrict__ x, const int* __restrict__ sl)
{
    int t = blockIdx.x, tid = threadIdx.x;
    for (int idx = tid; idx < 16384; idx += 256) {
        int b = idx >> 7, kk = idx & 127;
        float v = (t < sl[b]) ? x[((size_t)b * Tc + t) * Ic + kk] : 0.0f;
        __half hi = __float2half(v);
        __half lo = __float2half(v - __half2float(hi));
        int kg = kk >> 6;
        uint32_t off = swz((uint32_t)(b * 128 + (kk & 63) * 2));
        *(__half*)(g_xsp + (((size_t)t * 2 + 0) * 2 + kg) * 16384 + off) = hi;
        *(__half*)(g_xsp + (((size_t)t * 2 + 1) * 2 + kg) * 16384 + off) = lo;
    }
}

// ---------------- prologue: split hn into g_hsp[0] ----------------
__global__ void __launch_bounds__(256, 1) split_h0(const float* __restrict__ hn)
{
    int b = blockIdx.x, tid = threadIdx.x;
    for (int kk = tid; kk < 1024; kk += 256) {
        float v = hn[(size_t)b * Hc + kk];
        __half hi = __float2half(v);
        __half lo = __float2half(v - __half2float(hi));
        int kg = kk >> 6;
        uint32_t off = swz((uint32_t)(b * 128 + (kk & 63) * 2));
        *(__half*)(g_hsp + ((size_t)(0 * 2 + 0) * 16 + kg) * 16384 + off) = hi;
        *(__half*)(g_hsp + ((size_t)(0 * 2 + 1) * 16 + kg) * 16384 + off) = lo;
    }
}

// ---------------- persistent mma.sync kernel (fp16, 2-pass, 4-buf pipeline) ----------------
__global__ void __launch_bounds__(256, 1) persist_kernel(
    const int* __restrict__ sl, const float* __restrict__ cn,
    const float* __restrict__ bout, float* __restrict__ out)
{
    extern __shared__ unsigned char smc[];
    const uint32_t sWu = s2u(smc);
    const uint32_t sAu = sWu + SM_A;
    __shared__ float bias_s[32];
    __shared__ int sls[128];

    int cb = blockIdx.x, tid = threadIdx.x;
    int lane = tid & 31, wid = tid >> 5;
    bool isY = (cb >= 128);
    int cy = cb - 128;
    int mrow = (wid >> 1) << 5;
    int ncol = (wid & 1) << 4;

    if (tid < 128) sls[tid] = sl[tid];
    if (tid < 32) bias_s[tid] = isY ? bout[cy * 32 + tid] : g_bp[cb * 32 + tid];

    // load resident W plane (73728 B = 18 uint4/thread)
    {
        const uint4* ws4 = (const uint4*)(isY ? (g_Wosp + (size_t)cy * 73728)
                                              : (g_Wsp + (size_t)cb * 73728));
        uint4* wd4 = (uint4*)smc;
#pragma unroll
        for (int i = 0; i < 18; i++) wd4[i * 256 + tid] = ws4[i * 256 + tid];
    }

    uint32_t aB0 = sAu + (uint32_t)((mrow + (lane & 15)) * 128);
    uint32_t aB1 = aB0 + 16 * 128;
    uint32_t ax = (((uint32_t)lane >> 4) << 4) ^ (((uint32_t)lane & 7) << 4);
    uint32_t bn = (uint32_t)(ncol + (lane & 7));
    uint32_t bB0 = sWu + bn * 2304;
    uint32_t bB1 = bB0 + 8 * 2304;
    uint32_t bx = ((((uint32_t)lane >> 3) & 1) << 4) ^ (((uint32_t)lane & 7) << 4);

    float c_reg[4];
    if (!isY) {
#pragma unroll
        for (int v = 0; v < 2; v++) {
            int q = tid * 2 + v;
            int b = q >> 2, jp = (q & 3) << 1;
            c_reg[v * 2 + 0] = cn[(size_t)b * Hc + cb * 8 + jp];
            c_reg[v * 2 + 1] = cn[(size_t)b * Hc + cb * 8 + jp + 1];
        }
    }
    __syncthreads();

    const int NC = isY ? 16 : 18;

#pragma unroll 1
    for (int t = 0; t <= Tc; t++) {
        bool active = isY ? (t > 0) : (t < Tc);
        if (active) {
            int par = t & 1;

            auto stage = [&](int c) {
#pragma unroll
                for (int p = 0; p < 2; p++) {
                    const unsigned char* src;
                    if (!isY && c >= 16)
                        src = g_xsp + (((size_t)t * 2 + p) * 2 + (c - 16)) * 16384;
                    else
                        src = g_hsp + (((size_t)par * 2 + p) * 16 + c) * 16384;
                    uint32_t dst = sAu + (uint32_t)((c & 3) * 32768 + p * 16384 + tid * 16);
                    const unsigned char* s = src + tid * 16;
#pragma unroll
                    for (int i = 0; i < 4; i++)
                        CP16(dst + i * 4096, s + i * 4096);
                }
                CPCOMMIT();
            };

            stage(0); stage(1); stage(2);

            float d00[4], d01[4], d10[4], d11[4];
#pragma unroll
            for (int i = 0; i < 4; i++) { d00[i] = 0.f; d01[i] = 0.f; d10[i] = 0.f; d11[i] = 0.f; }

#pragma unroll 1
            for (int c = 0; c < NC; c++) {
                // ensure chunk c complete: pending allowed = min(2, NC-1-c)
                if (c < NC - 2)      { CPWAIT(2); }
                else if (c == NC - 2){ CPWAIT(1); }
                else                 { CPWAIT(0); }
                __syncthreads();   // all warps done with chunk c-1 & see chunk c data
                if (c + 3 < NC) stage(c + 3);

                uint32_t sOff = (uint32_t)((c & 3) * 32768);
                uint32_t kbase = (uint32_t)(c * 128);
#pragma unroll
                for (int kt = 0; kt < 4; kt++) {
                    uint32_t ko = ((uint32_t)(kt * 32)) ^ ax;
                    uint32_t kb = kbase + (((uint32_t)(kt * 32)) ^ bx);
                    uint32_t Ah0[4], Ah1[4], Al0[4], Al1[4], Bh0[2], Bh1[2];
                    ldm_x4(Ah0, aB0 + sOff + ko);
                    ldm_x4(Ah1, aB1 + sOff + ko);
                    ldm_x4(Al0, aB0 + sOff + 16384 + ko);
                    ldm_x4(Al1, aB1 + sOff + 16384 + ko);
                    ldm_x2(Bh0, bB0 + kb);
                    ldm_x2(Bh1, bB1 + kb);
                    mma16816(d00, Ah0, Bh0); mma16816(d01, Ah0, Bh1);
                    mma16816(d10, Ah1, Bh0); mma16816(d11, Ah1, Bh1);
                    mma16816(d00, Al0, Bh0); mma16816(d01, Al0, Bh1);
                    mma16816(d10, Al1, Bh0); mma16816(d11, Al1, Bh1);
                }
            }
            __syncthreads();   // all compute done before epilogue reuses A smem

            if (!isY) {
                float* gsh = (float*)(smc + SM_A);
                int mfr = mrow + (lane >> 2);
                int nfr = ncol + ((lane & 3) << 1);
                float* dp[4] = { d00, d01, d10, d11 };
#pragma unroll
                for (int mt = 0; mt < 2; mt++)
#pragma unroll
                    for (int nt = 0; nt < 2; nt++) {
                        float* dd = dp[mt * 2 + nt];
                        int m0 = mfr + mt * 16;
                        int n0 = nfr + nt * 8;
                        gsh[m0 * 33 + n0]           = dd[0] + bias_s[n0];
                        gsh[m0 * 33 + n0 + 1]       = dd[1] + bias_s[n0 + 1];
                        gsh[(m0 + 8) * 33 + n0]     = dd[2] + bias_s[n0];
                        gsh[(m0 + 8) * 33 + n0 + 1] = dd[3] + bias_s[n0 + 1];
                    }
                __syncthreads();

                int nxt = par ^ 1;
#pragma unroll
                for (int v = 0; v < 2; v++) {
                    int q = tid * 2 + v;
                    int b = q >> 2, jp = (q & 3) << 1;
                    float hv[2];
#pragma unroll
                    for (int w2 = 0; w2 < 2; w2++) {
                        int jj = jp + w2;
                        float gi = gsh[b * 33 + jj];
                        float gf = gsh[b * 33 + 8 + jj];
                        float gg = gsh[b * 33 + 16 + jj];
                        float go = gsh[b * 33 + 24 + jj];
                        if (t == 0) {
                            const float* g0 = g_g0 + (size_t)b * 4096 + cb * 32;
                            gi += g0[jj]; gf += g0[8 + jj]; gg += g0[16 + jj]; go += g0[24 + jj];
                        }
                        float cc = sigm(gf) * c_reg[v * 2 + w2] + sigm(gi) * tanhf(gg);
                        c_reg[v * 2 + w2] = cc;
                        hv[w2] = sigm(go) * tanhf(cc);
                    }
                    int j0 = cb * 8 + jp;
                    int ch = j0 >> 6, kin = j0 & 63;
                    uint32_t off = swz((uint32_t)(b * 128 + kin * 2));
                    __half h0 = __float2half(hv[0]);
                    __half h1 = __float2half(hv[1]);
                    __half l0 = __float2half(hv[0] - __half2float(h0));
                    __half l1 = __float2half(hv[1] - __half2float(h1));
                    unsigned int hi2 = ((unsigned int)hfu(h1) << 16) | hfu(h0);
                    unsigned int lo2 = ((unsigned int)hfu(l1) << 16) | hfu(l0);
                    __stcg((unsigned int*)(g_hsp + (((size_t)nxt * 2 + 0) * 16 + ch) * 16384 + off), hi2);
                    __stcg((unsigned int*)(g_hsp + (((size_t)nxt * 2 + 1) * 16 + ch) * 16384 + off), lo2);
                }
            } else {
                int tt = t - 1;
                int mfr = mrow + (lane >> 2);
                int nfr = ncol + ((lane & 3) << 1);
                float* dp[4] = { d00, d01, d10, d11 };
#pragma unroll
                for (int mt = 0; mt < 2; mt++)
#pragma unroll
                    for (int nt = 0; nt < 2; nt++) {
                        float* dd = dp[mt * 2 + nt];
                        int b0r = mfr + mt * 16;
                        int n0 = nfr + nt * 8;
                        float mk0 = (tt < sls[b0r]) ? 1.0f : 0.0f;
                        float mk1 = (tt < sls[b0r + 8]) ? 1.0f : 0.0f;
                        float2 v0, v1;
                        v0.x = (dd[0] + bias_s[n0]) * mk0;
                        v0.y = (dd[1] + bias_s[n0 + 1]) * mk0;
                        v1.x = (dd[2] + bias_s[n0]) * mk1;
                        v1.y = (dd[3] + bias_s[n0 + 1]) * mk1;
                        *(float2*)(out + ((size_t)b0r * Tc + tt) * 128 + cy * 32 + n0) = v0;
                        *(float2*)(out + ((size_t)(b0r + 8) * Tc + tt) * 128 + cy * 32 + n0) = v1;
                    }
            }
        }
        grid_sync();
    }
}

// ---------------- launch ----------------
extern "C" void kernel_launch(void* const* d_in, const int* in_sizes, int n_in,
                              void* d_out, int out_size) {
    const float* x    = (const float*)d_in[0];
    const int*   sl   = (const int*)  d_in[1];
    const float* hn   = (const float*)d_in[2];
    const float* cn   = (const float*)d_in[3];
    const float* outt = (const float*)d_in[4];
    const float* Wih  = (const float*)d_in[5];
    const float* Whh  = (const float*)d_in[6];
    const float* bih  = (const float*)d_in[7];
    const float* bhh  = (const float*)d_in[8];
    const float* Wout = (const float*)d_in[9];
    const float* bout = (const float*)d_in[10];
    float* out = (float*)d_out;

    cudaFuncSetAttribute(persist_kernel,
                         cudaFuncAttributeMaxDynamicSharedMemorySize, SMEM_BYTES);
    pack_weights<<<128, 256>>>(Wih, Whh, bih, bhh, Wout, bout);
    delta_init<<<128, 256>>>(hn, outt, Wout, bout);
    g0_init<<<128, 256>>>();
    split_w<<<132, 256>>>(Wout);
    split_x<<<1024, 256>>>(x, sl);
    split_h0<<<128, 256>>>(hn);
    persist_kernel<<<NBLK, 256, SMEM_BYTES>>>(sl, cn, bout, out);
}

// round 14
// speedup vs baseline: 8.5936x; 1.3542x over previous
#include <cuda_runtime.h>
#include <cuda_fp16.h>
#include <math.h>
#include <stdint.h>

#define Bc 128
#define Tc 1024
#define Ic 128
#define Hc 1024
#define KW 1280        // packed K in g_W: 1024 W_eff + 128 W_x + 128 W_o
#define NBLK 132       // 128 gate CTAs + 4 y CTAs

#define SM_W 147456                      // resident W hi+lo fp16 planes
#define SMEM_BYTES (SM_W + 4*16384)      // + 4 A buffers (16KB each) = 212992

typedef unsigned long long ull;

// ---------------- device scratch (static) ----------------
__device__ float g_W[(size_t)4096 * KW];
__device__ float g_bp[4096];
__device__ float g_delta[Bc * 128];
__device__ float g_g0[(size_t)Bc * 4096];
// pre-swizzled fp16 planes (A side: single hi plane)
__device__ __align__(16) unsigned char g_hsp[2 * 16 * 16384];             // [par][chunk][16KB]
__device__ __align__(16) unsigned char g_xsp[(size_t)Tc * 2 * 16384];     // [t][chunk][16KB]
__device__ __align__(16) unsigned char g_Wsp[(size_t)128 * 147456];       // [cb][plane][32][2304]
__device__ __align__(16) unsigned char g_Wosp[(size_t)4 * 147456];        // [cy][plane][32][2304]

__device__ unsigned g_cnt = 0;
__device__ volatile unsigned g_gen = 0;

// ---------------- helpers ----------------
__device__ __forceinline__ uint32_t swz(uint32_t b) { return b ^ ((b >> 3) & 0x70); }
__device__ __forceinline__ uint32_t s2u(const void* p) { return (uint32_t)__cvta_generic_to_shared(p); }
__device__ __forceinline__ float sigm(float v) { return 1.0f / (1.0f + expf(-v)); }
__device__ __forceinline__ unsigned short hfu(__half h) { return *(unsigned short*)&h; }

#define GADDR(r, n) ((r) * 32 + ((n) ^ (((r) & 7) << 2)))

__device__ __forceinline__ void grid_sync() {
    __syncthreads();
    if (threadIdx.x == 0) {
        __threadfence();
        unsigned my = g_gen;
        if (atomicAdd(&g_cnt, 1) == NBLK - 1) {
            g_cnt = 0;
            __threadfence();
            g_gen = my + 1;
        } else {
            while (g_gen == my) { }
        }
        __threadfence();
    }
    __syncthreads();
}

__device__ __forceinline__ void ldm_x4(uint32_t* r, uint32_t a) {
    asm volatile("ldmatrix.sync.aligned.m8n8.x4.shared.b16 {%0,%1,%2,%3}, [%4];"
                 : "=r"(r[0]), "=r"(r[1]), "=r"(r[2]), "=r"(r[3]) : "r"(a));
}
__device__ __forceinline__ void ldm_x2(uint32_t* r, uint32_t a) {
    asm volatile("ldmatrix.sync.aligned.m8n8.x2.shared.b16 {%0,%1}, [%2];"
                 : "=r"(r[0]), "=r"(r[1]) : "r"(a));
}
__device__ __forceinline__ void mma16816(float* d, const uint32_t* a, const uint32_t* b) {
    asm volatile("mma.sync.aligned.m16n8k16.row.col.f32.f16.f16.f32 "
                 "{%0,%1,%2,%3}, {%4,%5,%6,%7}, {%8,%9}, {%0,%1,%2,%3};"
                 : "+f"(d[0]), "+f"(d[1]), "+f"(d[2]), "+f"(d[3])
                 : "r"(a[0]), "r"(a[1]), "r"(a[2]), "r"(a[3]), "r"(b[0]), "r"(b[1]));
}

#define CP16(dst, src) asm volatile("cp.async.cg.shared.global [%0], [%1], 16;" :: "r"(dst), "l"(src))
#define CPCOMMIT() asm volatile("cp.async.commit_group;")
#define CPWAIT(n)  asm volatile("cp.async.wait_group %0;" :: "n"(n))
#define PBAR(id)   asm volatile("bar.sync %0, 64;" :: "r"(id) : "memory")

// ---------------- prologue: pack effective weights (grouped) ----------------
__global__ void __launch_bounds__(256, 1) pack_weights(
    const float* __restrict__ Wih, const float* __restrict__ Whh,
    const float* __restrict__ bih, const float* __restrict__ bhh,
    const float* __restrict__ Wout, const float* __restrict__ bout)
{
    __shared__ float ao[32][129];
    __shared__ float wos[128][33];
    int cb = blockIdx.x, tid = threadIdx.x;

    for (int i = 0; i < 4; i++) {
        int idx = i * 256 + tid;
        int r = idx >> 5, c4 = idx & 31;
        int gr = ((r >> 3) << 10) + (cb << 3) + (r & 7);
        float4 v = *(const float4*)(Wih + (size_t)gr * 256 + 128 + (c4 << 2));
        ao[r][(c4 << 2) + 0] = v.x; ao[r][(c4 << 2) + 1] = v.y;
        ao[r][(c4 << 2) + 2] = v.z; ao[r][(c4 << 2) + 3] = v.w;
    }
    __syncthreads();

    int r = tid >> 3;
    int gr = ((r >> 3) << 10) + (cb << 3) + (r & 7);
    int kk0 = (tid & 7) << 2;
    for (int kc = 0; kc < 32; kc++) {
        for (int i = 0; i < 4; i++) {
            int idx = i * 256 + tid;
            int o = idx >> 3, c4 = idx & 7;
            float4 v = *(const float4*)(Wout + (size_t)o * Hc + (kc << 5) + (c4 << 2));
            wos[o][(c4 << 2) + 0] = v.x; wos[o][(c4 << 2) + 1] = v.y;
            wos[o][(c4 << 2) + 2] = v.z; wos[o][(c4 << 2) + 3] = v.w;
        }
        __syncthreads();
        float a0 = 0.f, a1 = 0.f, a2 = 0.f, a3 = 0.f;
#pragma unroll 4
        for (int o = 0; o < 128; o++) {
            float a = ao[r][o];
            a0 += a * wos[o][kk0 + 0]; a1 += a * wos[o][kk0 + 1];
            a2 += a * wos[o][kk0 + 2]; a3 += a * wos[o][kk0 + 3];
        }
        int k = (kc << 5) + kk0;
        const float* hh = Whh + (size_t)gr * Hc + k;
        float* dst = g_W + (size_t)(cb * 32 + r) * KW + k;
        dst[0] = hh[0] + a0; dst[1] = hh[1] + a1;
        dst[2] = hh[2] + a2; dst[3] = hh[3] + a3;
        __syncthreads();
    }
    for (int i = 0; i < 8; i++) {
        int idx = i * 256 + tid;
        int rr = idx >> 6, c4 = idx & 63;
        int grr = ((rr >> 3) << 10) + (cb << 3) + (rr & 7);
        float4 v = *(const float4*)(Wih + (size_t)grr * 256 + (c4 << 2));
        *(float4*)(g_W + (size_t)(cb * 32 + rr) * KW + 1024 + (c4 << 2)) = v;
    }
    if (tid < 32) {
        int grr = ((tid >> 3) << 10) + (cb << 3) + (tid & 7);
        float s = bih[grr] + bhh[grr];
        for (int o = 0; o < 128; o++) s += ao[tid][o] * bout[o];
        g_bp[cb * 32 + tid] = s;
    }
}

// ---------------- prologue: delta ----------------
__global__ void __launch_bounds__(256, 1) delta_init(
    const float* __restrict__ hn, const float* __restrict__ outt,
    const float* __restrict__ Wout, const float* __restrict__ bout)
{
    __shared__ __align__(16) float hs[Hc];
    int b = blockIdx.x, tid = threadIdx.x;
    for (int k = tid; k < Hc; k += 256) hs[k] = hn[(size_t)b * Hc + k];
    __syncthreads();
    if (tid < 128) {
        int o = tid;
        const float4* wr = (const float4*)(Wout + (size_t)o * Hc);
        const float4* hv = (const float4*)hs;
        float s = 0.f;
        for (int k = 0; k < 256; k++) {
            float4 a = hv[k], w = wr[k];
            s += a.x * w.x + a.y * w.y + a.z * w.z + a.w * w.w;
        }
        g_delta[b * 128 + o] = outt[b * 128 + o] - bout[o] - s;
    }
}

// ---------------- prologue: g0 = delta @ W_o^T (grouped) ----------------
__global__ void __launch_bounds__(256, 1) g0_init()
{
    __shared__ float ws[32][132];
    int cb = blockIdx.x, tid = threadIdx.x;
    for (int i = tid; i < 32 * 128; i += 256) {
        int n = i >> 7, o = i & 127;
        ws[n][o] = g_W[(size_t)(cb * 32 + n) * KW + 1152 + o];
    }
    __syncthreads();
    int b = tid >> 1, nh = (tid & 1) * 16;
    float acc[16];
#pragma unroll
    for (int n = 0; n < 16; n++) acc[n] = 0.f;
    for (int o = 0; o < 128; o++) {
        float dv = g_delta[b * 128 + o];
#pragma unroll
        for (int n = 0; n < 16; n++) acc[n] += dv * ws[nh + n][o];
    }
    for (int n = 0; n < 16; n++)
        g_g0[(size_t)b * 4096 + cb * 32 + nh + n] = acc[n];
}

// ---------------- prologue: split weights to fp16 hi/lo planes ----------------
__global__ void __launch_bounds__(256, 1) split_w(const float* __restrict__ Wout)
{
    int bx = blockIdx.x, tid = threadIdx.x;
    if (bx < 128) {
        int cb = bx;
        for (int i = tid; i < 32 * 1152; i += 256) {
            int n = i / 1152, k = i % 1152;
            float v = g_W[(size_t)(cb * 32 + n) * KW + k];
            __half hi = __float2half(v);
            __half lo = __float2half(v - __half2float(hi));
            uint32_t off = (uint32_t)(n * 2304) + (((uint32_t)(k * 2)) ^ ((n & 7) << 4));
            unsigned char* base = g_Wsp + (size_t)cb * 147456;
            *(__half*)(base + off) = hi;
            *(__half*)(base + 73728 + off) = lo;
        }
    } else {
        int cy = bx - 128;
        for (int i = tid; i < 32 * 1024; i += 256) {
            int n = i >> 10, k = i & 1023;
            float v = Wout[(size_t)(cy * 32 + n) * Hc + k];
            __half hi = __float2half(v);
            __half lo = __float2half(v - __half2float(hi));
            uint32_t off = (uint32_t)(n * 2304) + (((uint32_t)(k * 2)) ^ ((n & 7) << 4));
            unsigned char* base = g_Wosp + (size_t)cy * 147456;
            *(__half*)(base + off) = hi;
            *(__half*)(base + 73728 + off) = lo;
        }
    }
}

// ---------------- prologue: split x (masked), single hi plane ----------------
__global__ void __launch_bounds__(256, 1) split_x(
    const float* __restrict__ x, const int* __restrict__ sl)
{
    int t = blockIdx.x, tid = threadIdx.x;
    for (int idx = tid; idx < 16384; idx += 256) {
        int b = idx >> 7, kk = idx & 127;
        float v = (t < sl[b]) ? x[((size_t)b * Tc + t) * Ic + kk] : 0.0f;
        int kg = kk >> 6;
        uint32_t off = swz((uint32_t)(b * 128 + (kk & 63) * 2));
        *(__half*)(g_xsp + ((size_t)t * 2 + kg) * 16384 + off) = __float2half(v);
    }
}

// ---------------- prologue: split hn into g_hsp[0], hi plane ----------------
__global__ void __launch_bounds__(256, 1) split_h0(const float* __restrict__ hn)
{
    int b = blockIdx.x, tid = threadIdx.x;
    for (int kk = tid; kk < 1024; kk += 256) {
        float v = hn[(size_t)b * Hc + kk];
        int kg = kk >> 6;
        uint32_t off = swz((uint32_t)(b * 128 + (kk & 63) * 2));
        *(__half*)(g_hsp + (size_t)kg * 16384 + off) = __float2half(v);
    }
}

// ---------------- persistent mma.sync kernel (pair-local pipelines) ----------------
__global__ void __launch_bounds__(256, 1) persist_kernel(
    const int* __restrict__ sl, const float* __restrict__ cn,
    const float* __restrict__ bout, float* __restrict__ out)
{
    extern __shared__ unsigned char smc[];
    const uint32_t sWu = s2u(smc);
    const uint32_t sAu = sWu + SM_W;
    __shared__ float bias_s[32];
    __shared__ int sls[128];

    int cb = blockIdx.x, tid = threadIdx.x;
    int lane = tid & 31, wid = tid >> 5;
    int p = wid >> 1, t64 = tid & 63;
    bool isY = (cb >= 128);
    int cy = cb - 128;
    int mrow = p << 5;
    int ncol = (wid & 1) << 4;
    int barid = p + 1;

    if (tid < 128) sls[tid] = sl[tid];
    if (tid < 32) bias_s[tid] = isY ? bout[cy * 32 + tid] : g_bp[cb * 32 + tid];

    // resident W hi/lo planes (147456 B = 36 uint4/thread)
    {
        const uint4* ws4 = (const uint4*)(isY ? (g_Wosp + (size_t)cy * 147456)
                                              : (g_Wsp + (size_t)cb * 147456));
        uint4* wd4 = (uint4*)smc;
#pragma unroll
        for (int i = 0; i < 36; i++) wd4[i * 256 + tid] = ws4[i * 256 + tid];
    }

    uint32_t aB0 = sAu + (uint32_t)((mrow + (lane & 15)) * 128);
    uint32_t aB1 = aB0 + 16 * 128;
    uint32_t ax = (((uint32_t)lane >> 4) << 4) ^ (((uint32_t)lane & 7) << 4);
    uint32_t bB0 = sWu + (uint32_t)(ncol + (lane & 7)) * 2304;
    uint32_t bB1 = bB0 + 8 * 2304;
    uint32_t bx = ((((uint32_t)lane >> 3) & 1) << 4) ^ (((uint32_t)lane & 7) << 4);

    float c_reg[4];
    if (!isY) {
        int bb = (p << 5) + (t64 >> 1);
        int jj0 = (t64 & 1) << 2;
#pragma unroll
        for (int v = 0; v < 4; v++)
            c_reg[v] = cn[(size_t)bb * Hc + (cb << 3) + jj0 + v];
    }
    __syncthreads();

    const int NC = isY ? 16 : 18;

    // pair-local stage: 4KB of chunk c for this pair's rows
    auto stage = [&](int c, const unsigned char* src) {
        uint32_t dst = sAu + (uint32_t)(((c & 3) << 14) + (p << 12) + t64 * 16);
        const unsigned char* s = src + (p << 12) + t64 * 16;
        CP16(dst, s); CP16(dst + 1024, s + 1024);
        CP16(dst + 2048, s + 2048); CP16(dst + 3072, s + 3072);
        CPCOMMIT();
    };

    // initial x prefetch for t=0 (gates)
    if (!isY) { stage(0, g_xsp); stage(1, g_xsp + 16384); }

#pragma unroll 1
    for (int t = 0; t <= Tc; t++) {
        bool active = isY ? (t > 0) : (t < Tc);
        if (active) {
            int par = t & 1;
            const unsigned char* hbase = g_hsp + (size_t)par * 16 * 16384;

            if (!isY) {
                stage(2, hbase);            // h chunk 0
            } else {
                stage(0, hbase); stage(1, hbase + 16384); stage(2, hbase + 2 * 16384);
            }

            float d00[4], d01[4], d10[4], d11[4];
#pragma unroll
            for (int i = 0; i < 4; i++) { d00[i] = 0.f; d01[i] = 0.f; d10[i] = 0.f; d11[i] = 0.f; }

#pragma unroll 1
            for (int c = 0; c < NC; c++) {
                if (c < NC - 2)       { CPWAIT(2); }
                else if (c == NC - 2) { CPWAIT(1); }
                else                  { CPWAIT(0); }
                PBAR(barid);
                if (c + 3 < NC) {
                    int cn3 = c + 3;
                    const unsigned char* src = isY ? (hbase + (size_t)cn3 * 16384)
                                                   : (hbase + (size_t)(cn3 - 2) * 16384);
                    stage(cn3, src);
                }
                uint32_t sOff = (uint32_t)((c & 3) << 14);
                uint32_t kbase = isY ? (uint32_t)(c << 7)
                                     : ((c < 2) ? (uint32_t)(2048 + (c << 7))
                                                : (uint32_t)((c - 2) << 7));
#pragma unroll
                for (int kt = 0; kt < 4; kt++) {
                    uint32_t ko = ((uint32_t)(kt * 32)) ^ ax;
                    uint32_t kb = kbase + (((uint32_t)(kt * 32)) ^ bx);
                    uint32_t Ah0[4], Ah1[4], Bh0[2], Bh1[2], Bl0[2], Bl1[2];
                    ldm_x4(Ah0, aB0 + sOff + ko);
                    ldm_x4(Ah1, aB1 + sOff + ko);
                    ldm_x2(Bh0, bB0 + kb);
                    ldm_x2(Bh1, bB1 + kb);
                    ldm_x2(Bl0, bB0 + 73728 + kb);
                    ldm_x2(Bl1, bB1 + 73728 + kb);
                    mma16816(d00, Ah0, Bh0); mma16816(d01, Ah0, Bh1);
                    mma16816(d10, Ah1, Bh0); mma16816(d11, Ah1, Bh1);
                    mma16816(d00, Ah0, Bl0); mma16816(d01, Ah0, Bl1);
                    mma16816(d10, Ah1, Bl0); mma16816(d11, Ah1, Bl1);
                }
            }

            if (!isY) {
                // pair-local gate exchange in buf3's pair region (dead after c=15)
                float* gshp = (float*)(smc + SM_W + 3 * 16384 + (p << 12));
                {
                    int rl = lane >> 2;
                    int nfr = ncol + ((lane & 3) << 1);
                    float* dp[4] = { d00, d01, d10, d11 };
#pragma unroll
                    for (int mt = 0; mt < 2; mt++)
#pragma unroll
                        for (int nt = 0; nt < 2; nt++) {
                            float* dd = dp[mt * 2 + nt];
                            int r0 = rl + mt * 16;
                            int n0 = nfr + nt * 8;
                            gshp[GADDR(r0, n0)]         = dd[0] + bias_s[n0];
                            gshp[GADDR(r0, n0 + 1)]     = dd[1] + bias_s[n0 + 1];
                            gshp[GADDR(r0 + 8, n0)]     = dd[2] + bias_s[n0];
                            gshp[GADDR(r0 + 8, n0 + 1)] = dd[3] + bias_s[n0 + 1];
                        }
                }
                PBAR(barid);

                int nxt = par ^ 1;
                int bl = t64 >> 1;
                int jj0 = (t64 & 1) << 2;
                int bb = (p << 5) + bl;
                float hv[4];
#pragma unroll
                for (int v = 0; v < 4; v++) {
                    int jj = jj0 + v;
                    float gi = gshp[GADDR(bl, jj)];
                    float gf = gshp[GADDR(bl, 8 + jj)];
                    float gg = gshp[GADDR(bl, 16 + jj)];
                    float go = gshp[GADDR(bl, 24 + jj)];
                    if (t == 0) {
                        const float* g0 = g_g0 + (size_t)bb * 4096 + (cb << 5);
                        gi += g0[jj]; gf += g0[8 + jj]; gg += g0[16 + jj]; go += g0[24 + jj];
                    }
                    float cc = sigm(gf) * c_reg[v] + sigm(gi) * tanhf(gg);
                    c_reg[v] = cc;
                    hv[v] = sigm(go) * tanhf(cc);
                }
                int j0 = (cb << 3) + jj0;
                int ch = j0 >> 6;
                uint32_t off = swz((uint32_t)(bb * 128 + (j0 & 63) * 2));
                ull pk = (ull)hfu(__float2half(hv[0]))
                       | ((ull)hfu(__float2half(hv[1])) << 16)
                       | ((ull)hfu(__float2half(hv[2])) << 32)
                       | ((ull)hfu(__float2half(hv[3])) << 48);
                __stcg((ull*)(g_hsp + ((size_t)nxt * 16 + ch) * 16384 + off), pk);

                // prefetch next step's x chunks (bufs 0,1 are free for this pair)
                if (t + 1 < Tc) {
                    stage(0, g_xsp + ((size_t)(t + 1) * 2 + 0) * 16384);
                    stage(1, g_xsp + ((size_t)(t + 1) * 2 + 1) * 16384);
                }
            } else {
                int tt = t - 1;
                int mfr = mrow + (lane >> 2);
                int nfr = ncol + ((lane & 3) << 1);
                float* dp[4] = { d00, d01, d10, d11 };
#pragma unroll
                for (int mt = 0; mt < 2; mt++)
#pragma unroll
                    for (int nt = 0; nt < 2; nt++) {
                        float* dd = dp[mt * 2 + nt];
                        int b0r = mfr + mt * 16;
                        int n0 = nfr + nt * 8;
                        float mk0 = (tt < sls[b0r]) ? 1.0f : 0.0f;
                        float mk1 = (tt < sls[b0r + 8]) ? 1.0f : 0.0f;
                        float2 v0, v1;
                        v0.x = (dd[0] + bias_s[n0]) * mk0;
                        v0.y = (dd[1] + bias_s[n0 + 1]) * mk0;
                        v1.x = (dd[2] + bias_s[n0]) * mk1;
                        v1.y = (dd[3] + bias_s[n0 + 1]) * mk1;
                        *(float2*)(out + ((size_t)b0r * Tc + tt) * 128 + cy * 32 + n0) = v0;
                        *(float2*)(out + ((size_t)(b0r + 8) * Tc + tt) * 128 + cy * 32 + n0) = v1;
                    }
            }
        }
        grid_sync();
    }
}

// ---------------- launch ----------------
extern "C" void kernel_launch(void* const* d_in, const int* in_sizes, int n_in,
                              void* d_out, int out_size) {
    const float* x    = (const float*)d_in[0];
    const int*   sl   = (const int*)  d_in[1];
    const float* hn   = (const float*)d_in[2];
    const float* cn   = (const float*)d_in[3];
    const float* outt = (const float*)d_in[4];
    const float* Wih  = (const float*)d_in[5];
    const float* Whh  = (const float*)d_in[6];
    const float* bih  = (const float*)d_in[7];
    const float* bhh  = (const float*)d_in[8];
    const float* Wout = (const float*)d_in[9];
    const float* bout = (const float*)d_in[10];
    float* out = (float*)d_out;

    cudaFuncSetAttribute(persist_kernel,
                         cudaFuncAttributeMaxDynamicSharedMemorySize, SMEM_BYTES);
    pack_weights<<<128, 256>>>(Wih, Whh, bih, bhh, Wout, bout);
    delta_init<<<128, 256>>>(hn, outt, Wout, bout);
    g0_init<<<128, 256>>>();
    split_w<<<132, 256>>>(Wout);
    split_x<<<1024, 256>>>(x, sl);
    split_h0<<<128, 256>>>(hn);
    persist_kernel<<<NBLK, 256, SMEM_BYTES>>>(sl, cn, bout, out);
}

// round 15
// speedup vs baseline: 11.2745x; 1.3120x over previous
#include <cuda_runtime.h>
#include <cuda_fp16.h>
#include <math.h>
#include <stdint.h>

#define Bc 128
#define Tc 1024
#define Ic 128
#define Hc 1024
#define KW 1280        // packed K in g_W: 1024 W_eff + 128 W_x + 128 W_o
#define NBLK 132       // 128 gate CTAs + 4 y CTAs

#define SM_W 73728                       // resident W fp16 (single hi plane)
#define SMEM_BYTES (SM_W + 4*16384)      // + 4 A buffers (16KB each) = 139264

typedef unsigned long long ull;

// ---------------- device scratch (static) ----------------
__device__ float g_W[(size_t)4096 * KW];
__device__ float g_bp[4096];
__device__ float g_delta[Bc * 128];
__device__ float g_g0[(size_t)Bc * 4096];
// pre-swizzled fp16 planes (single hi plane everywhere)
__device__ __align__(16) unsigned char g_hsp[2 * 16 * 16384];             // [par][chunk][16KB]
__device__ __align__(16) unsigned char g_xsp[(size_t)Tc * 2 * 16384];     // [t][chunk][16KB]
__device__ __align__(16) unsigned char g_Wsp[(size_t)128 * 73728];        // [cb][32][2304]
__device__ __align__(16) unsigned char g_Wosp[(size_t)4 * 73728];         // [cy][32][2304]

__device__ unsigned g_cnt = 0;
__device__ unsigned g_gen = 0;

// ---------------- helpers ----------------
__device__ __forceinline__ uint32_t swz(uint32_t b) { return b ^ ((b >> 3) & 0x70); }
__device__ __forceinline__ uint32_t s2u(const void* p) { return (uint32_t)__cvta_generic_to_shared(p); }
__device__ __forceinline__ float sigm(float v) { return 1.0f / (1.0f + expf(-v)); }
__device__ __forceinline__ unsigned short hfu(__half h) { return *(unsigned short*)&h; }

#define GADDR(r, n) ((r) * 32 + ((n) ^ (((r) & 7) << 2)))

// release/acquire grid barrier (no threadfence, no CCTL.IVALL)
__device__ __forceinline__ unsigned ld_acq(unsigned* p) {
    unsigned v;
    asm volatile("ld.acquire.gpu.global.u32 %0, [%1];" : "=r"(v) : "l"(p) : "memory");
    return v;
}
__device__ __forceinline__ void st_rel(unsigned* p, unsigned v) {
    asm volatile("st.release.gpu.global.u32 [%0], %1;" :: "l"(p), "r"(v) : "memory");
}
__device__ __forceinline__ unsigned atom_add_rel(unsigned* p, unsigned v) {
    unsigned old;
    asm volatile("atom.release.gpu.global.add.u32 %0, [%1], %2;"
                 : "=r"(old) : "l"(p), "r"(v) : "memory");
    return old;
}
__device__ __forceinline__ void grid_sync() {
    __syncthreads();
    if (threadIdx.x == 0) {
        unsigned my = ld_acq(&g_gen);
        if (atom_add_rel(&g_cnt, 1) == NBLK - 1) {
            g_cnt = 0;
            st_rel(&g_gen, my + 1);
        } else {
            while (ld_acq(&g_gen) == my) { }
        }
    }
    __syncthreads();
}

__device__ __forceinline__ void ldm_x4(uint32_t* r, uint32_t a) {
    asm volatile("ldmatrix.sync.aligned.m8n8.x4.shared.b16 {%0,%1,%2,%3}, [%4];"
                 : "=r"(r[0]), "=r"(r[1]), "=r"(r[2]), "=r"(r[3]) : "r"(a));
}
__device__ __forceinline__ void ldm_x2(uint32_t* r, uint32_t a) {
    asm volatile("ldmatrix.sync.aligned.m8n8.x2.shared.b16 {%0,%1}, [%2];"
                 : "=r"(r[0]), "=r"(r[1]) : "r"(a));
}
__device__ __forceinline__ void mma16816(float* d, const uint32_t* a, const uint32_t* b) {
    asm volatile("mma.sync.aligned.m16n8k16.row.col.f32.f16.f16.f32 "
                 "{%0,%1,%2,%3}, {%4,%5,%6,%7}, {%8,%9}, {%0,%1,%2,%3};"
                 : "+f"(d[0]), "+f"(d[1]), "+f"(d[2]), "+f"(d[3])
                 : "r"(a[0]), "r"(a[1]), "r"(a[2]), "r"(a[3]), "r"(b[0]), "r"(b[1]));
}

#define CP16(dst, src) asm volatile("cp.async.cg.shared.global [%0], [%1], 16;" :: "r"(dst), "l"(src))
#define CPCOMMIT() asm volatile("cp.async.commit_group;")
#define CPWAIT(n)  asm volatile("cp.async.wait_group %0;" :: "n"(n))
#define PBAR(id)   asm volatile("bar.sync %0, 64;" :: "r"(id) : "memory")

// ---------------- prologue: pack effective weights (grouped) ----------------
__global__ void __launch_bounds__(256, 1) pack_weights(
    const float* __restrict__ Wih, const float* __restrict__ Whh,
    const float* __restrict__ bih, const float* __restrict__ bhh,
    const float* __restrict__ Wout, const float* __restrict__ bout)
{
    __shared__ float ao[32][129];
    __shared__ float wos[128][33];
    int cb = blockIdx.x, tid = threadIdx.x;

    for (int i = 0; i < 4; i++) {
        int idx = i * 256 + tid;
        int r = idx >> 5, c4 = idx & 31;
        int gr = ((r >> 3) << 10) + (cb << 3) + (r & 7);
        float4 v = *(const float4*)(Wih + (size_t)gr * 256 + 128 + (c4 << 2));
        ao[r][(c4 << 2) + 0] = v.x; ao[r][(c4 << 2) + 1] = v.y;
        ao[r][(c4 << 2) + 2] = v.z; ao[r][(c4 << 2) + 3] = v.w;
    }
    __syncthreads();

    int r = tid >> 3;
    int gr = ((r >> 3) << 10) + (cb << 3) + (r & 7);
    int kk0 = (tid & 7) << 2;
    for (int kc = 0; kc < 32; kc++) {
        for (int i = 0; i < 4; i++) {
            int idx = i * 256 + tid;
            int o = idx >> 3, c4 = idx & 7;
            float4 v = *(const float4*)(Wout + (size_t)o * Hc + (kc << 5) + (c4 << 2));
            wos[o][(c4 << 2) + 0] = v.x; wos[o][(c4 << 2) + 1] = v.y;
            wos[o][(c4 << 2) + 2] = v.z; wos[o][(c4 << 2) + 3] = v.w;
        }
        __syncthreads();
        float a0 = 0.f, a1 = 0.f, a2 = 0.f, a3 = 0.f;
#pragma unroll 4
        for (int o = 0; o < 128; o++) {
            float a = ao[r][o];
            a0 += a * wos[o][kk0 + 0]; a1 += a * wos[o][kk0 + 1];
            a2 += a * wos[o][kk0 + 2]; a3 += a * wos[o][kk0 + 3];
        }
        int k = (kc << 5) + kk0;
        const float* hh = Whh + (size_t)gr * Hc + k;
        float* dst = g_W + (size_t)(cb * 32 + r) * KW + k;
        dst[0] = hh[0] + a0; dst[1] = hh[1] + a1;
        dst[2] = hh[2] + a2; dst[3] = hh[3] + a3;
        __syncthreads();
    }
    for (int i = 0; i < 8; i++) {
        int idx = i * 256 + tid;
        int rr = idx >> 6, c4 = idx & 63;
        int grr = ((rr >> 3) << 10) + (cb << 3) + (rr & 7);
        float4 v = *(const float4*)(Wih + (size_t)grr * 256 + (c4 << 2));
        *(float4*)(g_W + (size_t)(cb * 32 + rr) * KW + 1024 + (c4 << 2)) = v;
    }
    if (tid < 32) {
        int grr = ((tid >> 3) << 10) + (cb << 3) + (tid & 7);
        float s = bih[grr] + bhh[grr];
        for (int o = 0; o < 128; o++) s += ao[tid][o] * bout[o];
        g_bp[cb * 32 + tid] = s;
    }
}

// ---------------- prologue: delta ----------------
__global__ void __launch_bounds__(256, 1) delta_init(
    const float* __restrict__ hn, const float* __restrict__ outt,
    const float* __restrict__ Wout, const float* __restrict__ bout)
{
    __shared__ __align__(16) float hs[Hc];
    int b = blockIdx.x, tid = threadIdx.x;
    for (int k = tid; k < Hc; k += 256) hs[k] = hn[(size_t)b * Hc + k];
    __syncthreads();
    if (tid < 128) {
        int o = tid;
        const float4* wr = (const float4*)(Wout + (size_t)o * Hc);
        const float4* hv = (const float4*)hs;
        float s = 0.f;
        for (int k = 0; k < 256; k++) {
            float4 a = hv[k], w = wr[k];
            s += a.x * w.x + a.y * w.y + a.z * w.z + a.w * w.w;
        }
        g_delta[b * 128 + o] = outt[b * 128 + o] - bout[o] - s;
    }
}

// ---------------- prologue: g0 = delta @ W_o^T (grouped) ----------------
__global__ void __launch_bounds__(256, 1) g0_init()
{
    __shared__ float ws[32][132];
    int cb = blockIdx.x, tid = threadIdx.x;
    for (int i = tid; i < 32 * 128; i += 256) {
        int n = i >> 7, o = i & 127;
        ws[n][o] = g_W[(size_t)(cb * 32 + n) * KW + 1152 + o];
    }
    __syncthreads();
    int b = tid >> 1, nh = (tid & 1) * 16;
    float acc[16];
#pragma unroll
    for (int n = 0; n < 16; n++) acc[n] = 0.f;
    for (int o = 0; o < 128; o++) {
        float dv = g_delta[b * 128 + o];
#pragma unroll
        for (int n = 0; n < 16; n++) acc[n] += dv * ws[nh + n][o];
    }
    for (int n = 0; n < 16; n++)
        g_g0[(size_t)b * 4096 + cb * 32 + nh + n] = acc[n];
}

// ---------------- prologue: split weights to single fp16 plane ----------------
__global__ void __launch_bounds__(256, 1) split_w(const float* __restrict__ Wout)
{
    int bx = blockIdx.x, tid = threadIdx.x;
    if (bx < 128) {
        int cb = bx;
        for (int i = tid; i < 32 * 1152; i += 256) {
            int n = i / 1152, k = i % 1152;
            float v = g_W[(size_t)(cb * 32 + n) * KW + k];
            uint32_t off = (uint32_t)(n * 2304) + (((uint32_t)(k * 2)) ^ ((n & 7) << 4));
            *(__half*)(g_Wsp + (size_t)cb * 73728 + off) = __float2half(v);
        }
    } else {
        int cy = bx - 128;
        for (int i = tid; i < 32 * 1024; i += 256) {
            int n = i >> 10, k = i & 1023;
            float v = Wout[(size_t)(cy * 32 + n) * Hc + k];
            uint32_t off = (uint32_t)(n * 2304) + (((uint32_t)(k * 2)) ^ ((n & 7) << 4));
            *(__half*)(g_Wosp + (size_t)cy * 73728 + off) = __float2half(v);
        }
    }
}

// ---------------- prologue: split x (masked), single hi plane ----------------
__global__ void __launch_bounds__(256, 1) split_x(
    const float* __restrict__ x, const int* __restrict__ sl)
{
    int t = blockIdx.x, tid = threadIdx.x;
    for (int idx = tid; idx < 16384; idx += 256) {
        int b = idx >> 7, kk = idx & 127;
        float v = (t < sl[b]) ? x[((size_t)b * Tc + t) * Ic + kk] : 0.0f;
        int kg = kk >> 6;
        uint32_t off = swz((uint32_t)(b * 128 + (kk & 63) * 2));
        *(__half*)(g_xsp + ((size_t)t * 2 + kg) * 16384 + off) = __float2half(v);
    }
}

// ---------------- prologue: split hn into g_hsp[0], hi plane ----------------
__global__ void __launch_bounds__(256, 1) split_h0(const float* __restrict__ hn)
{
    int b = blockIdx.x, tid = threadIdx.x;
    for (int kk = tid; kk < 1024; kk += 256) {
        float v = hn[(size_t)b * Hc + kk];
        int kg = kk >> 6;
        uint32_t off = swz((uint32_t)(b * 128 + (kk & 63) * 2));
        *(__half*)(g_hsp + (size_t)kg * 16384 + off) = __float2half(v);
    }
}

// ---------------- persistent mma.sync kernel (1-pass fp16, pair-local) ----------------
__global__ void __launch_bounds__(256, 1) persist_kernel(
    const int* __restrict__ sl, const float* __restrict__ cn,
    const float* __restrict__ bout, float* __restrict__ out)
{
    extern __shared__ unsigned char smc[];
    const uint32_t sWu = s2u(smc);
    const uint32_t sAu = sWu + SM_W;
    __shared__ float bias_s[32];
    __shared__ int sls[128];

    int cb = blockIdx.x, tid = threadIdx.x;
    int lane = tid & 31, wid = tid >> 5;
    int p = wid >> 1, t64 = tid & 63;
    bool isY = (cb >= 128);
    int cy = cb - 128;
    int mrow = p << 5;
    int ncol = (wid & 1) << 4;
    int barid = p + 1;

    if (tid < 128) sls[tid] = sl[tid];
    if (tid < 32) bias_s[tid] = isY ? bout[cy * 32 + tid] : g_bp[cb * 32 + tid];

    // resident W single plane (73728 B = 18 uint4/thread)
    {
        const uint4* ws4 = (const uint4*)(isY ? (g_Wosp + (size_t)cy * 73728)
                                              : (g_Wsp + (size_t)cb * 73728));
        uint4* wd4 = (uint4*)smc;
#pragma unroll
        for (int i = 0; i < 18; i++) wd4[i * 256 + tid] = ws4[i * 256 + tid];
    }

    uint32_t aB0 = sAu + (uint32_t)((mrow + (lane & 15)) * 128);
    uint32_t aB1 = aB0 + 16 * 128;
    uint32_t ax = (((uint32_t)lane >> 4) << 4) ^ (((uint32_t)lane & 7) << 4);
    uint32_t bB0 = sWu + (uint32_t)(ncol + (lane & 7)) * 2304;
    uint32_t bB1 = bB0 + 8 * 2304;
    uint32_t bx = ((((uint32_t)lane >> 3) & 1) << 4) ^ (((uint32_t)lane & 7) << 4);

    float c_reg[4];
    if (!isY) {
        int bb = (p << 5) + (t64 >> 1);
        int jj0 = (t64 & 1) << 2;
#pragma unroll
        for (int v = 0; v < 4; v++)
            c_reg[v] = cn[(size_t)bb * Hc + (cb << 3) + jj0 + v];
    }
    __syncthreads();

    const int NC = isY ? 16 : 18;

    // pair-local stage: 4KB of chunk c for this pair's rows
    auto stage = [&](int c, const unsigned char* src) {
        uint32_t dst = sAu + (uint32_t)(((c & 3) << 14) + (p << 12) + t64 * 16);
        const unsigned char* s = src + (p << 12) + t64 * 16;
        CP16(dst, s); CP16(dst + 1024, s + 1024);
        CP16(dst + 2048, s + 2048); CP16(dst + 3072, s + 3072);
        CPCOMMIT();
    };

    // initial x prefetch for t=0 (gates)
    if (!isY) { stage(0, g_xsp); stage(1, g_xsp + 16384); }

#pragma unroll 1
    for (int t = 0; t <= Tc; t++) {
        bool active = isY ? (t > 0) : (t < Tc);
        if (active) {
            int par = t & 1;
            const unsigned char* hbase = g_hsp + (size_t)par * 16 * 16384;

            if (!isY) {
                stage(2, hbase);            // h chunk 0
            } else {
                stage(0, hbase); stage(1, hbase + 16384); stage(2, hbase + 2 * 16384);
            }

            float d00[4], d01[4], d10[4], d11[4];
#pragma unroll
            for (int i = 0; i < 4; i++) { d00[i] = 0.f; d01[i] = 0.f; d10[i] = 0.f; d11[i] = 0.f; }

#pragma unroll 1
            for (int c = 0; c < NC; c++) {
                if (c < NC - 2)       { CPWAIT(2); }
                else if (c == NC - 2) { CPWAIT(1); }
                else                  { CPWAIT(0); }
                PBAR(barid);
                if (c + 3 < NC) {
                    int cn3 = c + 3;
                    const unsigned char* src = isY ? (hbase + (size_t)cn3 * 16384)
                                                   : (hbase + (size_t)(cn3 - 2) * 16384);
                    stage(cn3, src);
                }
                uint32_t sOff = (uint32_t)((c & 3) << 14);
                uint32_t kbase = isY ? (uint32_t)(c << 7)
                                     : ((c < 2) ? (uint32_t)(2048 + (c << 7))
                                                : (uint32_t)((c - 2) << 7));
#pragma unroll
                for (int kt = 0; kt < 4; kt++) {
                    uint32_t ko = ((uint32_t)(kt * 32)) ^ ax;
                    uint32_t kb = kbase + (((uint32_t)(kt * 32)) ^ bx);
                    uint32_t Ah0[4], Ah1[4], Bh0[2], Bh1[2];
                    ldm_x4(Ah0, aB0 + sOff + ko);
                    ldm_x4(Ah1, aB1 + sOff + ko);
                    ldm_x2(Bh0, bB0 + kb);
                    ldm_x2(Bh1, bB1 + kb);
                    mma16816(d00, Ah0, Bh0); mma16816(d01, Ah0, Bh1);
                    mma16816(d10, Ah1, Bh0); mma16816(d11, Ah1, Bh1);
                }
            }

            if (!isY) {
                // pair-local gate exchange in buf3's pair region (dead after c=15)
                float* gshp = (float*)(smc + SM_W + 3 * 16384 + (p << 12));
                {
                    int rl = lane >> 2;
                    int nfr = ncol + ((lane & 3) << 1);
                    float* dp[4] = { d00, d01, d10, d11 };
#pragma unroll
                    for (int mt = 0; mt < 2; mt++)
#pragma unroll
                        for (int nt = 0; nt < 2; nt++) {
                            float* dd = dp[mt * 2 + nt];
                            int r0 = rl + mt * 16;
                            int n0 = nfr + nt * 8;
                            gshp[GADDR(r0, n0)]         = dd[0] + bias_s[n0];
                            gshp[GADDR(r0, n0 + 1)]     = dd[1] + bias_s[n0 + 1];
                            gshp[GADDR(r0 + 8, n0)]     = dd[2] + bias_s[n0];
                            gshp[GADDR(r0 + 8, n0 + 1)] = dd[3] + bias_s[n0 + 1];
                        }
                }
                PBAR(barid);

                int nxt = par ^ 1;
                int bl = t64 >> 1;
                int jj0 = (t64 & 1) << 2;
                int bb = (p << 5) + bl;
                float hv[4];
#pragma unroll
                for (int v = 0; v < 4; v++) {
                    int jj = jj0 + v;
                    float gi = gshp[GADDR(bl, jj)];
                    float gf = gshp[GADDR(bl, 8 + jj)];
                    float gg = gshp[GADDR(bl, 16 + jj)];
                    float go = gshp[GADDR(bl, 24 + jj)];
                    if (t == 0) {
                        const float* g0 = g_g0 + (size_t)bb * 4096 + (cb << 5);
                        gi += g0[jj]; gf += g0[8 + jj]; gg += g0[16 + jj]; go += g0[24 + jj];
                    }
                    float cc = sigm(gf) * c_reg[v] + sigm(gi) * tanhf(gg);
                    c_reg[v] = cc;
                    hv[v] = sigm(go) * tanhf(cc);
                }
                int j0 = (cb << 3) + jj0;
                int ch = j0 >> 6;
                uint32_t off = swz((uint32_t)(bb * 128 + (j0 & 63) * 2));
                ull pk = (ull)hfu(__float2half(hv[0]))
                       | ((ull)hfu(__float2half(hv[1])) << 16)
                       | ((ull)hfu(__float2half(hv[2])) << 32)
                       | ((ull)hfu(__float2half(hv[3])) << 48);
                __stcg((ull*)(g_hsp + ((size_t)nxt * 16 + ch) * 16384 + off), pk);

                // prefetch next step's x chunks (bufs 0,1 are free for this pair)
                if (t + 1 < Tc) {
                    stage(0, g_xsp + ((size_t)(t + 1) * 2 + 0) * 16384);
                    stage(1, g_xsp + ((size_t)(t + 1) * 2 + 1) * 16384);
                }
            } else {
                int tt = t - 1;
                int mfr = mrow + (lane >> 2);
                int nfr = ncol + ((lane & 3) << 1);
                float* dp[4] = { d00, d01, d10, d11 };
#pragma unroll
                for (int mt = 0; mt < 2; mt++)
#pragma unroll
                    for (int nt = 0; nt < 2; nt++) {
                        float* dd = dp[mt * 2 + nt];
                        int b0r = mfr + mt * 16;
                        int n0 = nfr + nt * 8;
                        float mk0 = (tt < sls[b0r]) ? 1.0f : 0.0f;
                        float mk1 = (tt < sls[b0r + 8]) ? 1.0f : 0.0f;
                        float2 v0, v1;
                        v0.x = (dd[0] + bias_s[n0]) * mk0;
                        v0.y = (dd[1] + bias_s[n0 + 1]) * mk0;
                        v1.x = (dd[2] + bias_s[n0]) * mk1;
                        v1.y = (dd[3] + bias_s[n0 + 1]) * mk1;
                        *(float2*)(out + ((size_t)b0r * Tc + tt) * 128 + cy * 32 + n0) = v0;
                        *(float2*)(out + ((size_t)(b0r + 8) * Tc + tt) * 128 + cy * 32 + n0) = v1;
                    }
            }
        }
        grid_sync();
    }
}

// ---------------- launch ----------------
extern "C" void kernel_launch(void* const* d_in, const int* in_sizes, int n_in,
                              void* d_out, int out_size) {
    const float* x    = (const float*)d_in[0];
    const int*   sl   = (const int*)  d_in[1];
    const float* hn   = (const float*)d_in[2];
    const float* cn   = (const float*)d_in[3];
    const float* outt = (const float*)d_in[4];
    const float* Wih  = (const float*)d_in[5];
    const float* Whh  = (const float*)d_in[6];
    const float* bih  = (const float*)d_in[7];
    const float* bhh  = (const float*)d_in[8];
    const float* Wout = (const float*)d_in[9];
    const float* bout = (const float*)d_in[10];
    float* out = (float*)d_out;

    cudaFuncSetAttribute(persist_kernel,
                         cudaFuncAttributeMaxDynamicSharedMemorySize, SMEM_BYTES);
    pack_weights<<<128, 256>>>(Wih, Whh, bih, bhh, Wout, bout);
    delta_init<<<128, 256>>>(hn, outt, Wout, bout);
    g0_init<<<128, 256>>>();
    split_w<<<132, 256>>>(Wout);
    split_x<<<1024, 256>>>(x, sl);
    split_h0<<<128, 256>>>(hn);
    persist_kernel<<<NBLK, 256, SMEM_BYTES>>>(sl, cn, bout, out);
}